// round 13
// baseline (speedup 1.0000x reference)
#include <cuda_runtime.h>
#include <cuda_bf16.h>
#include <math.h>
#include <stdint.h>

// ---------------- problem constants ----------------
#define BB    4096
#define TT    96
#define FRAW  5
#define TOTF  11
#define HID   512
#define NL    4
#define HEADS 8
#define DH    64
#define PATCH 8
#define NPATCH 12
#define PDIM  88
#define PDIMP 96
#define TOK   (BB*NPATCH)   // 49152
#define MLPH  2048
#define NCLS  3

// ---------------- scratch (static device, no allocation) ----------------
__device__ float g_feats[(size_t)TOK*PDIMP];
__device__ float g_h  [(size_t)TOK*HID];
__device__ float g_h2 [(size_t)TOK*HID];
__device__ float g_n  [(size_t)TOK*HID];
__device__ float g_qkv[(size_t)TOK*3*HID];
__device__ float g_o  [(size_t)TOK*HID];
__device__ float g_g  [(size_t)TOK*MLPH];
__device__ float g_c1 [(size_t)BB*512];
__device__ float g_c2 [(size_t)BB*128];
// tf32-pre-rounded weight copies (same [K][N] layout; pe padded to 96 rows)
__device__ float g_pe_wr [(size_t)PDIMP*HID];
__device__ float g_qkv_wr[(size_t)NL*HID*3*HID];
__device__ float g_out_wr[(size_t)NL*HID*HID];
__device__ float g_m1_wr [(size_t)NL*HID*MLPH];
__device__ float g_m2_wr [(size_t)NL*MLPH*HID];
__device__ float g_c1_wr [(size_t)HID*NPATCH*512];
__device__ float g_c2_wr [(size_t)512*128];

__device__ __forceinline__ float gelu_f(float x) {
    return 0.5f * x * (1.f + erff(x * 0.7071067811865476f));
}
__device__ __forceinline__ float to_tf32(float x) {
    uint32_t u;
    asm("cvt.rna.tf32.f32 %0, %1;" : "=r"(u) : "f"(x));
    return __uint_as_float(u);
}
__device__ __forceinline__ uint32_t s2u(const void* p) {
    uint32_t a;
    asm("{ .reg .u64 t; cvta.to.shared.u64 t, %1; cvt.u32.u64 %0, t; }" : "=r"(a) : "l"(p));
    return a;
}
__device__ __forceinline__ void mma_tf32(float c[4], const uint32_t a[4], const uint32_t b[2]) {
    asm volatile(
        "mma.sync.aligned.m16n8k8.row.col.f32.tf32.tf32.f32 "
        "{%0,%1,%2,%3}, {%4,%5,%6,%7}, {%8,%9}, {%0,%1,%2,%3};"
        : "+f"(c[0]), "+f"(c[1]), "+f"(c[2]), "+f"(c[3])
        : "r"(a[0]), "r"(a[1]), "r"(a[2]), "r"(a[3]), "r"(b[0]), "r"(b[1]));
}

// ---------------- weight pre-round (vectorized) ---------------------------
__global__ void round_copy4(const float4* __restrict__ src, float4* __restrict__ dst, int n4)
{
    const int i = blockIdx.x * blockDim.x + threadIdx.x;
    if (i >= n4) return;
    float4 v = src[i];
    v.x = to_tf32(v.x); v.y = to_tf32(v.y); v.z = to_tf32(v.z); v.w = to_tf32(v.w);
    dst[i] = v;
}
// pe_w [88][512] -> [96][512] rounded, zero pad rows
__global__ void pad_pew_kernel(const float* __restrict__ pe_w, float* __restrict__ dst)
{
    const int idx = blockIdx.x * blockDim.x + threadIdx.x;
    if (idx >= PDIMP*HID) return;
    const int k = idx / HID;
    dst[idx] = (k < PDIM) ? to_tf32(pe_w[idx]) : 0.f;
}

// ---------------- pipelined tf32 tensor GEMM (256x128 tile) ---------------
// C = act(A@B + bias [+res]) [RND: round C to tf32]
// A: MxK row-major, PRE-ROUNDED tf32. B: KxN row-major, pre-rounded.
// M%256==0, N%128==0, K%16==0. 8 warps, warp tile 64x64, 4-stage cp.async.
#define SA 20     // As row stride (floats)
#define SB 136    // Bs row stride (floats)
#define STG_F (256*SA + 16*SB)   // floats per stage = 5120+2176 = 7296
#define NSTAGE 4
#define PIPE_SMEM (NSTAGE * STG_F * 4)   // 116736 B

template<int ACT, int RES, int RND>
__global__ void __launch_bounds__(256, 1) mma_gemm_pipe(
    const float* __restrict__ A, const float* __restrict__ Bw,
    const float* __restrict__ bias, const float* __restrict__ res,
    float* __restrict__ C, int M, int N, int K)
{
    extern __shared__ float dsm[];
    const int tid  = threadIdx.x;
    const int lane = tid & 31;
    const int wid  = tid >> 5;
    const int g    = lane >> 2;
    const int t4   = lane & 3;
    const int wm   = wid & 3;       // 4 warps along M (64 rows each)
    const int wn   = wid >> 2;      // 2 warps along N (64 cols each)
    const int mBase = wm * 64;
    const int nBase = wn * 64;

    const float* Ab = A  + (size_t)blockIdx.y * 256 * K;
    const float* Bb = Bw + (size_t)blockIdx.x * 128;
    const int nk = K >> 4;

    const uint32_t smemBase = s2u(dsm);

    // loader coords: A 256x16 = 1024 float4 (4/thread); B 16x128 = 512 float4 (2/thread)
    const int ar [4] = { tid>>2, (tid+256)>>2, (tid+512)>>2, (tid+768)>>2 };
    const int akq   = (tid & 3) * 4;
    const int bkr0 = tid >> 5,         bnq0 = (tid & 31) * 4;
    const int bkr1 = (tid + 256) >> 5, bnq1 = (tid & 31) * 4;

// macro-local var kbi (NOT kb) — must capture loop var, not shadow it
#define ISSUE(kb_) do {                                                           \
    const int kbi = (kb_);                                                        \
    if (kbi < nk) {                                                               \
        const int k0 = kbi << 4;                                                  \
        const uint32_t sA = smemBase + (uint32_t)((kbi % NSTAGE) * STG_F) * 4u;   \
        const uint32_t sB = sA + 256*SA*4;                                        \
        asm volatile("cp.async.cg.shared.global [%0], [%1], 16;" ::               \
            "r"(sA + (ar[0]*SA + akq)*4), "l"(Ab + (size_t)ar[0]*K + k0 + akq));  \
        asm volatile("cp.async.cg.shared.global [%0], [%1], 16;" ::               \
            "r"(sA + (ar[1]*SA + akq)*4), "l"(Ab + (size_t)ar[1]*K + k0 + akq));  \
        asm volatile("cp.async.cg.shared.global [%0], [%1], 16;" ::               \
            "r"(sA + (ar[2]*SA + akq)*4), "l"(Ab + (size_t)ar[2]*K + k0 + akq));  \
        asm volatile("cp.async.cg.shared.global [%0], [%1], 16;" ::               \
            "r"(sA + (ar[3]*SA + akq)*4), "l"(Ab + (size_t)ar[3]*K + k0 + akq));  \
        asm volatile("cp.async.cg.shared.global [%0], [%1], 16;" ::               \
            "r"(sB + (bkr0*SB + bnq0)*4), "l"(Bb + (size_t)(k0+bkr0)*N + bnq0));  \
        asm volatile("cp.async.cg.shared.global [%0], [%1], 16;" ::               \
            "r"(sB + (bkr1*SB + bnq1)*4), "l"(Bb + (size_t)(k0+bkr1)*N + bnq1));  \
    }                                                                             \
    asm volatile("cp.async.commit_group;" ::: "memory");                          \
} while (0)

    ISSUE(0);
    ISSUE(1);
    ISSUE(2);

    float acc[4][8][4] = {};

    for (int kb = 0; kb < nk; kb++) {
        asm volatile("cp.async.wait_group 2;" ::: "memory");
        __syncthreads();
        ISSUE(kb + 3);

        const float* As = dsm + (kb % NSTAGE) * STG_F;
        const float* Bs = As + 256*SA;

        #pragma unroll
        for (int kk = 0; kk < 16; kk += 8) {
            uint32_t af[4][4];
            #pragma unroll
            for (int mi = 0; mi < 4; mi++) {
                const int m0 = mBase + mi*16;
                af[mi][0] = __float_as_uint(As[(m0 + g    )*SA + kk + t4    ]);
                af[mi][1] = __float_as_uint(As[(m0 + g + 8)*SA + kk + t4    ]);
                af[mi][2] = __float_as_uint(As[(m0 + g    )*SA + kk + t4 + 4]);
                af[mi][3] = __float_as_uint(As[(m0 + g + 8)*SA + kk + t4 + 4]);
            }
            uint32_t bf[8][2];
            #pragma unroll
            for (int ni = 0; ni < 8; ni++) {
                const int n0 = nBase + ni*8 + g;
                bf[ni][0] = __float_as_uint(Bs[(kk + t4    )*SB + n0]);
                bf[ni][1] = __float_as_uint(Bs[(kk + t4 + 4)*SB + n0]);
            }
            #pragma unroll
            for (int mi = 0; mi < 4; mi++)
                #pragma unroll
                for (int ni = 0; ni < 8; ni++)
                    mma_tf32(acc[mi][ni], af[mi], bf[ni]);
        }
    }
#undef ISSUE

    // ---- epilogue ----
    const int rowTile = blockIdx.y * 256;
    const int colTile = blockIdx.x * 128;
    #pragma unroll
    for (int mi = 0; mi < 4; mi++) {
        const int r0 = rowTile + mBase + mi*16 + g;
        #pragma unroll
        for (int ni = 0; ni < 8; ni++) {
            const int c = colTile + nBase + ni*8 + t4*2;
            const float2 bz = *(const float2*)(bias + c);
            float v0 = acc[mi][ni][0] + bz.x;
            float v1 = acc[mi][ni][1] + bz.y;
            float v2 = acc[mi][ni][2] + bz.x;
            float v3 = acc[mi][ni][3] + bz.y;
            const size_t off0 = (size_t)r0 * N + c;
            const size_t off1 = (size_t)(r0 + 8) * N + c;
            if (RES) {
                const float2 r0v = *(const float2*)(res + off0);
                const float2 r1v = *(const float2*)(res + off1);
                v0 += r0v.x; v1 += r0v.y; v2 += r1v.x; v3 += r1v.y;
            }
            if (ACT == 1) {
                v0 = gelu_f(v0); v1 = gelu_f(v1);
                v2 = gelu_f(v2); v3 = gelu_f(v3);
            }
            if (RND) {
                v0 = to_tf32(v0); v1 = to_tf32(v1);
                v2 = to_tf32(v2); v3 = to_tf32(v3);
            }
            *(float2*)(C + off0) = make_float2(v0, v1);
            *(float2*)(C + off1) = make_float2(v2, v3);
        }
    }
}

// ---------------- synchronous tf32 GEMM (rounds A at staging) -------------
// used only where A is NOT pre-rounded (cls1: A = residual stream H)
#define SSA 20
#define SSB 136
template<int ACT, int RES, int RND>
__global__ void __launch_bounds__(256, 2) mma_gemm_sync(
    const float* __restrict__ A, const float* __restrict__ Bw,
    const float* __restrict__ bias, const float* __restrict__ res,
    float* __restrict__ C, int M, int N, int K)
{
    __shared__ float As[128][SSA];
    __shared__ float Bs[16][SSB];
    const int tid  = threadIdx.x;
    const int lane = tid & 31;
    const int wid  = tid >> 5;
    const int g    = lane >> 2;
    const int t4   = lane & 3;
    const int wm   = wid & 3;
    const int wn   = wid >> 2;
    const int mBase = wm * 32;
    const int nBase = wn * 64;

    const float* Ab = A  + (size_t)blockIdx.y * 128 * K;
    const float* Bb = Bw + (size_t)blockIdx.x * 128;

    float acc[2][8][4] = {};

    for (int k0 = 0; k0 < K; k0 += 16) {
        #pragma unroll
        for (int i = 0; i < 2; i++) {
            const int f = tid + i*256;
            const int r = f >> 2, kq = (f & 3) * 4;
            float4 v = *(const float4*)(Ab + (size_t)r*K + k0 + kq);
            v.x = to_tf32(v.x); v.y = to_tf32(v.y);
            v.z = to_tf32(v.z); v.w = to_tf32(v.w);
            *(float4*)(&As[r][kq]) = v;
        }
        #pragma unroll
        for (int i = 0; i < 2; i++) {
            const int f = tid + i*256;
            const int kr = f >> 5, nq = (f & 31) * 4;
            *(float4*)(&Bs[kr][nq]) = *(const float4*)(Bb + (size_t)(k0 + kr)*N + nq);
        }
        __syncthreads();

        #pragma unroll
        for (int kk = 0; kk < 16; kk += 8) {
            uint32_t af[2][4];
            #pragma unroll
            for (int mi = 0; mi < 2; mi++) {
                const int m0 = mBase + mi*16;
                af[mi][0] = __float_as_uint(As[m0 + g    ][kk + t4    ]);
                af[mi][1] = __float_as_uint(As[m0 + g + 8][kk + t4    ]);
                af[mi][2] = __float_as_uint(As[m0 + g    ][kk + t4 + 4]);
                af[mi][3] = __float_as_uint(As[m0 + g + 8][kk + t4 + 4]);
            }
            uint32_t bf[8][2];
            #pragma unroll
            for (int ni = 0; ni < 8; ni++) {
                const int n0 = nBase + ni*8 + g;
                bf[ni][0] = __float_as_uint(Bs[kk + t4    ][n0]);
                bf[ni][1] = __float_as_uint(Bs[kk + t4 + 4][n0]);
            }
            #pragma unroll
            for (int mi = 0; mi < 2; mi++)
                #pragma unroll
                for (int ni = 0; ni < 8; ni++)
                    mma_tf32(acc[mi][ni], af[mi], bf[ni]);
        }
        __syncthreads();
    }

    const int rowTile = blockIdx.y * 128;
    const int colTile = blockIdx.x * 128;
    #pragma unroll
    for (int mi = 0; mi < 2; mi++) {
        const int r0 = rowTile + mBase + mi*16 + g;
        #pragma unroll
        for (int ni = 0; ni < 8; ni++) {
            const int c = colTile + nBase + ni*8 + t4*2;
            const float2 bz = *(const float2*)(bias + c);
            float v0 = acc[mi][ni][0] + bz.x;
            float v1 = acc[mi][ni][1] + bz.y;
            float v2 = acc[mi][ni][2] + bz.x;
            float v3 = acc[mi][ni][3] + bz.y;
            const size_t off0 = (size_t)r0 * N + c;
            const size_t off1 = (size_t)(r0 + 8) * N + c;
            if (RES) {
                const float2 r0v = *(const float2*)(res + off0);
                const float2 r1v = *(const float2*)(res + off1);
                v0 += r0v.x; v1 += r0v.y; v2 += r1v.x; v3 += r1v.y;
            }
            if (ACT == 1) {
                v0 = gelu_f(v0); v1 = gelu_f(v1);
                v2 = gelu_f(v2); v3 = gelu_f(v3);
            }
            if (RND) {
                v0 = to_tf32(v0); v1 = to_tf32(v1);
                v2 = to_tf32(v2); v3 = to_tf32(v3);
            }
            *(float2*)(C + off0) = make_float2(v0, v1);
            *(float2*)(C + off1) = make_float2(v2, v3);
        }
    }
}

// ---------------- stage 1: factor engineering + time-norm ----------------
__global__ void factors_kernel(const float* __restrict__ x,
                               const float* __restrict__ in_w,
                               const float* __restrict__ in_b,
                               float* __restrict__ feats)
{
    __shared__ float cl[TT], vol[TT];
    __shared__ float sf[TT][TOTF];
    __shared__ float mean_s[TOTF], inv_s[TOTF];
    const int b = blockIdx.x;
    const int t = threadIdx.x;
    const float* xb = x + (size_t)b * TT * FRAW;

    if (t < TT) { cl[t] = xb[t*FRAW + 3]; vol[t] = xb[t*FRAW + 4]; }
    __syncthreads();

    if (t < TT) {
        const float a13 = 2.f/13.f, a27 = 2.f/27.f, a14 = 1.f/14.f;
        float e13 = cl[0], e27 = cl[0];
        float eg = 0.f, el = 0.f;
        for (int j = 1; j <= t; j++) {
            float c = cl[j];
            e13 = a13*c + (1.f - a13)*e13;
            e27 = a27*c + (1.f - a27)*e27;
            float d = c - cl[j-1];
            float g = fmaxf(d, 0.f);
            float l = -fminf(d, 0.f);
            eg = a14*g + (1.f - a14)*eg;
            el = a14*l + (1.f - a14)*el;
        }
        float macd = e13 - e27;
        float rs  = eg / (el + 1e-10f);
        float rsi = (100.f - 100.f/(1.f + rs)) * 0.01f;

        float bb = 0.f;
        if (t >= 19) {
            float s = 0.f, s2 = 0.f;
            for (int j = t-19; j <= t; j++) { float c = cl[j]; s += c; s2 += c*c; }
            float m  = s * 0.05f;
            float sq = s2 * 0.05f;
            float sd = sqrtf(fmaxf(sq - m*m, 0.f));
            bb = 4.f * sd / (m + 1e-8f);
        }

        float lr = 0.f, lv = 0.f;
        float svt = vol[t] > 0.f ? vol[t] : 1.f;
        if (t >= 1) {
            float pc = fmaxf(cl[t-1], 1e-8f);
            lr = logf(fmaxf(cl[t], 1e-8f) / pc);
            float svp = vol[t-1] > 0.f ? vol[t-1] : 1.f;
            lv = logf(svt / (svp + 1e-8f));
        }

        float vmr = 1.f;
        if (t >= 19) {
            float s = 0.f;
            for (int j = t-19; j <= t; j++) { float v2 = vol[j] > 0.f ? vol[j] : 1.f; s += v2; }
            vmr = svt / (s * 0.05f + 1e-8f);
        }

        float f6[6] = {macd, rsi, bb, lr, lv, vmr};
        #pragma unroll
        for (int f = 0; f < FRAW; f++) sf[t][f] = xb[t*FRAW + f];
        #pragma unroll
        for (int f = 0; f < 6; f++) {
            float v = f6[f];
            if (!isfinite(v)) v = 0.f;
            sf[t][FRAW + f] = v;
        }
    }
    __syncthreads();

    if (t < TOTF) {
        float s = 0.f;
        for (int j = 0; j < TT; j++) s += sf[j][t];
        mean_s[t] = s / (float)TT;
    }
    __syncthreads();
    if (t < TOTF) {
        float m = mean_s[t], s = 0.f;
        for (int j = 0; j < TT; j++) { float d = sf[j][t] - m; s += d*d; }
        inv_s[t] = rsqrtf(s / (float)TT + 1e-5f);
    }
    __syncthreads();

    if (t < TT) {
        const int token = b*NPATCH + (t / PATCH);
        float* o = feats + (size_t)token*PDIMP + (t % PATCH)*TOTF;
        #pragma unroll
        for (int f = 0; f < TOTF; f++)
            o[f] = to_tf32((sf[t][f] - mean_s[f]) * inv_s[f] * in_w[f] + in_b[f]);
    }
    if (t < NPATCH) {
        float* z = feats + (size_t)(b*NPATCH + t)*PDIMP + PDIM;
        #pragma unroll
        for (int i = 0; i < PDIMP - PDIM; i++) z[i] = 0.f;
    }
}

// ---------------- LayerNorm (output rounded; feeds GEMM A only) ----------
__global__ void __launch_bounds__(128) ln_kernel(const float* __restrict__ X,
                                                 const float* __restrict__ w,
                                                 const float* __restrict__ b,
                                                 float* __restrict__ Y)
{
    const int row = blockIdx.x;
    const int tid = threadIdx.x;
    const float4 v = ((const float4*)(X + (size_t)row*HID))[tid];
    float s = v.x + v.y + v.z + v.w;
    __shared__ float red[4], red2[4];
    #pragma unroll
    for (int o = 16; o; o >>= 1) s += __shfl_down_sync(0xffffffffu, s, o);
    if ((tid & 31) == 0) red[tid >> 5] = s;
    __syncthreads();
    const float m = (red[0]+red[1]+red[2]+red[3]) * (1.f/(float)HID);
    float dx = v.x - m, dy = v.y - m, dz = v.z - m, dw = v.w - m;
    float s2 = dx*dx + dy*dy + dz*dz + dw*dw;
    #pragma unroll
    for (int o = 16; o; o >>= 1) s2 += __shfl_down_sync(0xffffffffu, s2, o);
    if ((tid & 31) == 0) red2[tid >> 5] = s2;
    __syncthreads();
    const float var = (red2[0]+red2[1]+red2[2]+red2[3]) * (1.f/(float)HID);
    const float inv = rsqrtf(var + 1e-5f);
    const int c = tid * 4;
    const float4 wv = *(const float4*)(w + c);
    const float4 bv = *(const float4*)(b + c);
    float4 o4;
    o4.x = to_tf32(dx*inv*wv.x + bv.x);
    o4.y = to_tf32(dy*inv*wv.y + bv.y);
    o4.z = to_tf32(dz*inv*wv.z + bv.z);
    o4.w = to_tf32(dw*inv*wv.w + bv.w);
    ((float4*)(Y + (size_t)row*HID))[tid] = o4;
}

// ---------------- attention (output rounded; feeds GEMM A only) ----------
__global__ void __launch_bounds__(64) attn_kernel(const float* __restrict__ qkv,
                                                  float* __restrict__ out)
{
    const int bh = blockIdx.x;
    const int b = bh >> 3, h = bh & 7;
    const int tid = threadIdx.x;
    __shared__ float q[NPATCH][DH], k[NPATCH][DH], v[NPATCH][DH];
    __shared__ float att[NPATCH][NPATCH];

    const float* base = qkv + (size_t)(b*NPATCH) * (3*HID) + h*DH;
    for (int idx = tid; idx < NPATCH*DH; idx += 64) {
        int p = idx >> 6, d = idx & 63;
        q[p][d] = base[(size_t)p*(3*HID) + d];
        k[p][d] = base[(size_t)p*(3*HID) + HID + d];
        v[p][d] = base[(size_t)p*(3*HID) + 2*HID + d];
    }
    __syncthreads();

    for (int p = tid; p < NPATCH*NPATCH; p += 64) {
        int i = p / NPATCH, j = p % NPATCH;
        float s = 0.f;
        #pragma unroll
        for (int d = 0; d < DH; d++) s = fmaf(q[i][d], k[j][d], s);
        att[i][j] = s * 0.125f;
    }
    __syncthreads();

    if (tid < NPATCH) {
        float mx = -1e30f;
        #pragma unroll
        for (int j = 0; j < NPATCH; j++) mx = fmaxf(mx, att[tid][j]);
        float e[NPATCH], sum = 0.f;
        #pragma unroll
        for (int j = 0; j < NPATCH; j++) { e[j] = expf(att[tid][j] - mx); sum += e[j]; }
        const float r = 1.f / sum;
        #pragma unroll
        for (int j = 0; j < NPATCH; j++) att[tid][j] = e[j] * r;
    }
    __syncthreads();

    const int d = tid;
    #pragma unroll
    for (int i = 0; i < NPATCH; i++) {
        float s = 0.f;
        #pragma unroll
        for (int j = 0; j < NPATCH; j++) s = fmaf(att[i][j], v[j][d], s);
        out[(size_t)(b*NPATCH + i)*HID + h*DH + d] = to_tf32(s);
    }
}

// ---------------- final tiny GEMM: (4096x128)@(128x3) --------------------
__global__ void cls3_kernel(const float* __restrict__ C2,
                            const float* __restrict__ w3,
                            const float* __restrict__ b3,
                            float* __restrict__ out)
{
    const int idx = blockIdx.x * blockDim.x + threadIdx.x;
    if (idx >= BB*NCLS) return;
    const int b = idx / NCLS, c = idx % NCLS;
    float s = b3[c];
    const float* r = C2 + (size_t)b*128;
    #pragma unroll 8
    for (int k2 = 0; k2 < 128; k2++) s = fmaf(r[k2], w3[k2*NCLS + c], s);
    out[idx] = s;
}

// ---------------- host launcher ------------------------------------------
static inline float* sym_addr(const void* s) {
    void* p = nullptr;
    cudaGetSymbolAddress(&p, s);
    return (float*)p;
}

template<int ACT, int RES, int RND>
static void launch_pipe(const float* A, const float* B, const float* bias,
                        const float* res, float* C, int M, int N, int K)
{
    static bool attr_done = false;
    if (!attr_done) {
        cudaFuncSetAttribute(mma_gemm_pipe<ACT,RES,RND>,
                             cudaFuncAttributeMaxDynamicSharedMemorySize, PIPE_SMEM);
        attr_done = true;
    }
    mma_gemm_pipe<ACT,RES,RND><<<dim3(N/128, M/256), 256, PIPE_SMEM>>>(A, B, bias, res, C, M, N, K);
}

extern "C" void kernel_launch(void* const* d_in, const int* in_sizes, int n_in,
                              void* d_out, int out_size)
{
    const float* x      = (const float*)d_in[0];
    const float* in_w   = (const float*)d_in[1];
    const float* in_b   = (const float*)d_in[2];
    const float* pe_w   = (const float*)d_in[3];
    const float* pe_b   = (const float*)d_in[4];
    const float* ln1_w  = (const float*)d_in[5];
    const float* ln1_b  = (const float*)d_in[6];
    const float* qkv_w  = (const float*)d_in[7];
    const float* qkv_b  = (const float*)d_in[8];
    const float* out_w  = (const float*)d_in[9];
    const float* out_b  = (const float*)d_in[10];
    const float* ln2_w  = (const float*)d_in[11];
    const float* ln2_b  = (const float*)d_in[12];
    const float* mlp_w1 = (const float*)d_in[13];
    const float* mlp_b1 = (const float*)d_in[14];
    const float* mlp_w2 = (const float*)d_in[15];
    const float* mlp_b2 = (const float*)d_in[16];
    const float* cls_w1 = (const float*)d_in[17];
    const float* cls_b1 = (const float*)d_in[18];
    const float* cls_w2 = (const float*)d_in[19];
    const float* cls_b2 = (const float*)d_in[20];
    const float* cls_w3 = (const float*)d_in[21];
    const float* cls_b3 = (const float*)d_in[22];

    float* F   = sym_addr(g_feats);
    float* H   = sym_addr(g_h);
    float* H2  = sym_addr(g_h2);
    float* Nn  = sym_addr(g_n);
    float* QKV = sym_addr(g_qkv);
    float* O   = sym_addr(g_o);
    float* G   = sym_addr(g_g);
    float* C1  = sym_addr(g_c1);
    float* C2  = sym_addr(g_c2);
    float* PEr = sym_addr(g_pe_wr);
    float* QKr = sym_addr(g_qkv_wr);
    float* OUr = sym_addr(g_out_wr);
    float* M1r = sym_addr(g_m1_wr);
    float* M2r = sym_addr(g_m2_wr);
    float* C1r = sym_addr(g_c1_wr);
    float* C2r = sym_addr(g_c2_wr);

    // pre-round weights to tf32 (vectorized; pe padded 88->96 rows)
    pad_pew_kernel<<<(PDIMP*HID + 255)/256, 256>>>(pe_w, PEr);
    round_copy4<<<(NL*HID*3*HID/4 + 255)/256, 256>>>((const float4*)qkv_w,  (float4*)QKr, NL*HID*3*HID/4);
    round_copy4<<<(NL*HID*HID/4   + 255)/256, 256>>>((const float4*)out_w,  (float4*)OUr, NL*HID*HID/4);
    round_copy4<<<(NL*HID*MLPH/4  + 255)/256, 256>>>((const float4*)mlp_w1, (float4*)M1r, NL*HID*MLPH/4);
    round_copy4<<<(NL*MLPH*HID/4  + 255)/256, 256>>>((const float4*)mlp_w2, (float4*)M2r, NL*MLPH*HID/4);
    round_copy4<<<(HID*NPATCH*512/4 + 255)/256, 256>>>((const float4*)cls_w1, (float4*)C1r, HID*NPATCH*512/4);
    round_copy4<<<(512*128/4      + 255)/256, 256>>>((const float4*)cls_w2, (float4*)C2r, 512*128/4);

    factors_kernel<<<BB, TT>>>(x, in_w, in_b, F);

    // patch embed: (TOK x 96) @ (96 x 512)
    launch_pipe<0,0,0>(F, PEr, pe_b, nullptr, H, TOK, HID, PDIMP);

    for (int i = 0; i < NL; i++) {
        ln_kernel<<<TOK, 128>>>(H, ln1_w + i*HID, ln1_b + i*HID, Nn);
        launch_pipe<0,0,0>(Nn, QKr + (size_t)i*HID*3*HID, qkv_b + (size_t)i*3*HID,
                           nullptr, QKV, TOK, 3*HID, HID);
        attn_kernel<<<BB*HEADS, 64>>>(QKV, O);
        launch_pipe<0,1,0>(O, OUr + (size_t)i*HID*HID, out_b + (size_t)i*HID,
                           H, H2, TOK, HID, HID);
        ln_kernel<<<TOK, 128>>>(H2, ln2_w + i*HID, ln2_b + i*HID, Nn);
        launch_pipe<1,0,1>(Nn, M1r + (size_t)i*HID*MLPH, mlp_b1 + (size_t)i*MLPH,
                           nullptr, G, TOK, MLPH, HID);
        launch_pipe<0,1,0>(G, M2r + (size_t)i*MLPH*HID, mlp_b2 + (size_t)i*HID,
                           H2, H, TOK, HID, MLPH);
    }

    // classifier: H (fp32 residual stream) -> sync kernel rounds A at staging
    mma_gemm_sync<1,0,1><<<dim3(512/128, BB/128), 256>>>(
        H, C1r, cls_b1, nullptr, C1, BB, 512, HID*NPATCH);
    launch_pipe<1,0,1>(C1, C2r, cls_b2, nullptr, C2, BB, 128, 512);
    cls3_kernel<<<(BB*NCLS + 127)/128, 128>>>(C2, cls_w3, cls_b3, (float*)d_out);
}

// round 14
// speedup vs baseline: 1.6974x; 1.6974x over previous
#include <cuda_runtime.h>
#include <cuda_fp16.h>
#include <math.h>
#include <stdint.h>

// ---------------- problem constants ----------------
#define BB    4096
#define TT    96
#define FRAW  5
#define TOTF  11
#define HID   512
#define NL    4
#define HEADS 8
#define DH    64
#define PATCH 8
#define NPATCH 12
#define PDIM  88
#define PDIMP 96
#define TOK   (BB*NPATCH)   // 49152
#define MLPH  2048
#define NCLS  3

// ---------------- scratch (static device, no allocation) ----------------
// half activations (GEMM A inputs) + half transposed weights [N][K]
__device__ __align__(256) __half g_feats[(size_t)TOK*PDIMP];
__device__ __align__(256) __half g_n  [(size_t)TOK*HID];
__device__ __align__(256) __half g_o  [(size_t)TOK*HID];
__device__ __align__(256) __half g_g  [(size_t)TOK*MLPH];
__device__ __align__(256) __half g_hh [(size_t)TOK*HID];
__device__ __align__(256) __half g_c1 [(size_t)BB*512];
__device__ __align__(256) __half g_c2 [(size_t)BB*128];
__device__ __align__(256) __half g_pe_wt [(size_t)HID*PDIMP];
__device__ __align__(256) __half g_qkv_wt[(size_t)NL*3*HID*HID];
__device__ __align__(256) __half g_out_wt[(size_t)NL*HID*HID];
__device__ __align__(256) __half g_m1_wt [(size_t)NL*MLPH*HID];
__device__ __align__(256) __half g_m2_wt [(size_t)NL*HID*MLPH];
__device__ __align__(256) __half g_c1_wt [(size_t)512*HID*NPATCH];
__device__ __align__(256) __half g_c2_wt [(size_t)128*512];
// fp32 buffers
__device__ float g_h  [(size_t)TOK*HID];
__device__ float g_h2 [(size_t)TOK*HID];
__device__ float g_qkv[(size_t)TOK*3*HID];

__device__ __forceinline__ float gelu_f(float x) {
    return 0.5f * x * (1.f + erff(x * 0.7071067811865476f));
}
__device__ __forceinline__ uint32_t s2u(const void* p) {
    uint32_t a;
    asm("{ .reg .u64 t; cvta.to.shared.u64 t, %1; cvt.u32.u64 %0, t; }" : "=r"(a) : "l"(p));
    return a;
}
__device__ __forceinline__ void mma_f16(float c[4], const uint32_t a[4], const uint32_t b[2]) {
    asm volatile(
        "mma.sync.aligned.m16n8k16.row.col.f32.f16.f16.f32 "
        "{%0,%1,%2,%3}, {%4,%5,%6,%7}, {%8,%9}, {%0,%1,%2,%3};"
        : "+f"(c[0]), "+f"(c[1]), "+f"(c[2]), "+f"(c[3])
        : "r"(a[0]), "r"(a[1]), "r"(a[2]), "r"(a[3]), "r"(b[0]), "r"(b[1]));
}

// ---------------- weight prep: fp32 [K][N] -> half [N][Kp] (zero pad) -----
__global__ void transpose_half(const float* __restrict__ src, __half* __restrict__ dst,
                               int K, int N, int Kp)
{
    __shared__ float t[32][33];
    const int kBase = blockIdx.y*32, nBase = blockIdx.x*32;
    src += (size_t)blockIdx.z * K * N;
    dst += (size_t)blockIdx.z * N * Kp;
    for (int i = threadIdx.y; i < 32; i += 8) {
        int k = kBase + i, n = nBase + threadIdx.x;
        t[i][threadIdx.x] = (k < K && n < N) ? src[(size_t)k*N + n] : 0.f;
    }
    __syncthreads();
    for (int i = threadIdx.y; i < 32; i += 8) {
        int n = nBase + i, k = kBase + threadIdx.x;
        if (n < N && k < Kp) dst[(size_t)n*Kp + k] = __float2half_rn(t[threadIdx.x][i]);
    }
}

// ---------------- fp32 -> half convert (residual stream for cls1) --------
__global__ void f2h_kernel(const float4* __restrict__ src, __half2* __restrict__ dst, int n4)
{
    const int i = blockIdx.x * blockDim.x + threadIdx.x;
    if (i >= n4) return;
    const float4 v = src[i];
    dst[i*2]   = __floats2half2_rn(v.x, v.y);
    dst[i*2+1] = __floats2half2_rn(v.z, v.w);
}

// ---------------- pipelined fp16 tensor GEMM (NT) -------------------------
// C = act(A@Bt^T + bias [+res]); A: [M][K] half row-major (K contig),
// Bt: [N][K] half (K contig). M%128==0, N%128==0, K%32==0.
// 128x128 tile, BK=32, 8 warps (warp 32x64), 3-stage cp.async, 2 CTA/SM.
#define SAH 40                      // smem row stride in halfs (80B)
#define STG_HF (2*128*SAH)          // halfs per stage (A 128x40 + B 128x40) = 10240
#define STG_BYTES (STG_HF*2)        // 20480
#define NSTAGE 3
#define PIPE_SMEM (NSTAGE*STG_BYTES) // 61440

template<int ACT, int RES, int OUTH>
__global__ void __launch_bounds__(256, 2) hgemm_pipe(
    const __half* __restrict__ A, const __half* __restrict__ Bt,
    const float* __restrict__ bias, const float* __restrict__ res,
    void* __restrict__ Cv, int M, int N, int K)
{
    extern __shared__ __half hsm[];
    const int tid  = threadIdx.x;
    const int lane = tid & 31;
    const int wid  = tid >> 5;
    const int g    = lane >> 2;
    const int t4   = lane & 3;
    const int wm   = wid & 3;       // 4 warps along M (32 rows)
    const int wn   = wid >> 2;      // 2 warps along N (64 cols)
    const int mBase = wm * 32;
    const int nBase = wn * 64;

    const __half* Ab = A  + (size_t)blockIdx.y * 128 * K;
    const __half* Bb = Bt + (size_t)blockIdx.x * 128 * K;   // B tile = 128 N-rows
    const int nk = K >> 5;

    const uint32_t smemBase = s2u(hsm);

    // loader: A tile 128x32 halfs = 512 x 16B chunks, 2/thread; B same
    const int r0c = tid >> 2,         q0 = (tid & 3) * 8;   // halfs
    const int r1c = (tid + 256) >> 2, q1 = (tid & 3) * 8;

// macro-local kbi (NOT kb): must capture loop var, not shadow it
#define ISSUE(kb_) do {                                                            \
    const int kbi = (kb_);                                                         \
    if (kbi < nk) {                                                                \
        const int k0 = kbi << 5;                                                   \
        const uint32_t sA = smemBase + (uint32_t)((kbi % NSTAGE) * STG_BYTES);     \
        const uint32_t sB = sA + 128*SAH*2;                                        \
        asm volatile("cp.async.cg.shared.global [%0], [%1], 16;" ::                \
            "r"(sA + (uint32_t)(r0c*SAH + q0)*2), "l"(Ab + (size_t)r0c*K + k0 + q0)); \
        asm volatile("cp.async.cg.shared.global [%0], [%1], 16;" ::                \
            "r"(sA + (uint32_t)(r1c*SAH + q1)*2), "l"(Ab + (size_t)r1c*K + k0 + q1)); \
        asm volatile("cp.async.cg.shared.global [%0], [%1], 16;" ::                \
            "r"(sB + (uint32_t)(r0c*SAH + q0)*2), "l"(Bb + (size_t)r0c*K + k0 + q0)); \
        asm volatile("cp.async.cg.shared.global [%0], [%1], 16;" ::                \
            "r"(sB + (uint32_t)(r1c*SAH + q1)*2), "l"(Bb + (size_t)r1c*K + k0 + q1)); \
    }                                                                              \
    asm volatile("cp.async.commit_group;" ::: "memory");                           \
} while (0)

    ISSUE(0);
    ISSUE(1);

    float acc[2][8][4] = {};

    for (int kb = 0; kb < nk; kb++) {
        asm volatile("cp.async.wait_group 1;" ::: "memory");
        __syncthreads();
        ISSUE(kb + 2);

        const __half* As = hsm + (kb % NSTAGE) * STG_HF;
        const __half* Bs = As + 128*SAH;

        #pragma unroll
        for (int kk = 0; kk < 32; kk += 16) {
            uint32_t af[2][4];
            #pragma unroll
            for (int mi = 0; mi < 2; mi++) {
                const int m0 = mBase + mi*16;
                af[mi][0] = *(const uint32_t*)&As[(m0 + g    )*SAH + kk + 2*t4    ];
                af[mi][1] = *(const uint32_t*)&As[(m0 + g + 8)*SAH + kk + 2*t4    ];
                af[mi][2] = *(const uint32_t*)&As[(m0 + g    )*SAH + kk + 2*t4 + 8];
                af[mi][3] = *(const uint32_t*)&As[(m0 + g + 8)*SAH + kk + 2*t4 + 8];
            }
            uint32_t bf[8][2];
            #pragma unroll
            for (int ni = 0; ni < 8; ni++) {
                const int n0 = nBase + ni*8 + g;
                bf[ni][0] = *(const uint32_t*)&Bs[n0*SAH + kk + 2*t4    ];
                bf[ni][1] = *(const uint32_t*)&Bs[n0*SAH + kk + 2*t4 + 8];
            }
            #pragma unroll
            for (int mi = 0; mi < 2; mi++)
                #pragma unroll
                for (int ni = 0; ni < 8; ni++)
                    mma_f16(acc[mi][ni], af[mi], bf[ni]);
        }
    }
#undef ISSUE

    // ---- epilogue ----
    const int rowTile = blockIdx.y * 128;
    const int colTile = blockIdx.x * 128;
    #pragma unroll
    for (int mi = 0; mi < 2; mi++) {
        const int r0 = rowTile + mBase + mi*16 + g;
        #pragma unroll
        for (int ni = 0; ni < 8; ni++) {
            const int c = colTile + nBase + ni*8 + t4*2;
            const float2 bz = *(const float2*)(bias + c);
            float v0 = acc[mi][ni][0] + bz.x;
            float v1 = acc[mi][ni][1] + bz.y;
            float v2 = acc[mi][ni][2] + bz.x;
            float v3 = acc[mi][ni][3] + bz.y;
            const size_t off0 = (size_t)r0 * N + c;
            const size_t off1 = (size_t)(r0 + 8) * N + c;
            if (RES) {
                const float2 ra = *(const float2*)(res + off0);
                const float2 rb = *(const float2*)(res + off1);
                v0 += ra.x; v1 += ra.y; v2 += rb.x; v3 += rb.y;
            }
            if (ACT == 1) {
                v0 = gelu_f(v0); v1 = gelu_f(v1);
                v2 = gelu_f(v2); v3 = gelu_f(v3);
            }
            if (OUTH) {
                __half* C = (__half*)Cv;
                *(__half2*)(C + off0) = __floats2half2_rn(v0, v1);
                *(__half2*)(C + off1) = __floats2half2_rn(v2, v3);
            } else {
                float* C = (float*)Cv;
                *(float2*)(C + off0) = make_float2(v0, v1);
                *(float2*)(C + off1) = make_float2(v2, v3);
            }
        }
    }
}

// ---------------- stage 1: factor engineering + time-norm (half out) -----
__global__ void factors_kernel(const float* __restrict__ x,
                               const float* __restrict__ in_w,
                               const float* __restrict__ in_b,
                               __half* __restrict__ feats)
{
    __shared__ float cl[TT], vol[TT];
    __shared__ float sf[TT][TOTF];
    __shared__ float mean_s[TOTF], inv_s[TOTF];
    const int b = blockIdx.x;
    const int t = threadIdx.x;
    const float* xb = x + (size_t)b * TT * FRAW;

    if (t < TT) { cl[t] = xb[t*FRAW + 3]; vol[t] = xb[t*FRAW + 4]; }
    __syncthreads();

    if (t < TT) {
        const float a13 = 2.f/13.f, a27 = 2.f/27.f, a14 = 1.f/14.f;
        float e13 = cl[0], e27 = cl[0];
        float eg = 0.f, el = 0.f;
        for (int j = 1; j <= t; j++) {
            float c = cl[j];
            e13 = a13*c + (1.f - a13)*e13;
            e27 = a27*c + (1.f - a27)*e27;
            float d = c - cl[j-1];
            float gg = fmaxf(d, 0.f);
            float ll = -fminf(d, 0.f);
            eg = a14*gg + (1.f - a14)*eg;
            el = a14*ll + (1.f - a14)*el;
        }
        float macd = e13 - e27;
        float rs  = eg / (el + 1e-10f);
        float rsi = (100.f - 100.f/(1.f + rs)) * 0.01f;

        float bb = 0.f;
        if (t >= 19) {
            float s = 0.f, s2 = 0.f;
            for (int j = t-19; j <= t; j++) { float c = cl[j]; s += c; s2 += c*c; }
            float m  = s * 0.05f;
            float sq = s2 * 0.05f;
            float sd = sqrtf(fmaxf(sq - m*m, 0.f));
            bb = 4.f * sd / (m + 1e-8f);
        }

        float lr = 0.f, lv = 0.f;
        float svt = vol[t] > 0.f ? vol[t] : 1.f;
        if (t >= 1) {
            float pc = fmaxf(cl[t-1], 1e-8f);
            lr = logf(fmaxf(cl[t], 1e-8f) / pc);
            float svp = vol[t-1] > 0.f ? vol[t-1] : 1.f;
            lv = logf(svt / (svp + 1e-8f));
        }

        float vmr = 1.f;
        if (t >= 19) {
            float s = 0.f;
            for (int j = t-19; j <= t; j++) { float v2 = vol[j] > 0.f ? vol[j] : 1.f; s += v2; }
            vmr = svt / (s * 0.05f + 1e-8f);
        }

        float f6[6] = {macd, rsi, bb, lr, lv, vmr};
        #pragma unroll
        for (int f = 0; f < FRAW; f++) sf[t][f] = xb[t*FRAW + f];
        #pragma unroll
        for (int f = 0; f < 6; f++) {
            float v = f6[f];
            if (!isfinite(v)) v = 0.f;
            sf[t][FRAW + f] = v;
        }
    }
    __syncthreads();

    if (t < TOTF) {
        float s = 0.f;
        for (int j = 0; j < TT; j++) s += sf[j][t];
        mean_s[t] = s / (float)TT;
    }
    __syncthreads();
    if (t < TOTF) {
        float m = mean_s[t], s = 0.f;
        for (int j = 0; j < TT; j++) { float d = sf[j][t] - m; s += d*d; }
        inv_s[t] = rsqrtf(s / (float)TT + 1e-5f);
    }
    __syncthreads();

    if (t < TT) {
        const int token = b*NPATCH + (t / PATCH);
        __half* o = feats + (size_t)token*PDIMP + (t % PATCH)*TOTF;
        #pragma unroll
        for (int f = 0; f < TOTF; f++)
            o[f] = __float2half_rn((sf[t][f] - mean_s[f]) * inv_s[f] * in_w[f] + in_b[f]);
    }
    if (t < NPATCH) {
        __half* z = g_feats + (size_t)(b*NPATCH + t)*PDIMP + PDIM;
        #pragma unroll
        for (int i = 0; i < PDIMP - PDIM; i++) z[i] = __float2half_rn(0.f);
    }
}

// ---------------- LayerNorm: fp32 in, half out ----------------------------
__global__ void __launch_bounds__(128) ln_kernel(const float* __restrict__ X,
                                                 const float* __restrict__ w,
                                                 const float* __restrict__ b,
                                                 __half* __restrict__ Y)
{
    const int row = blockIdx.x;
    const int tid = threadIdx.x;
    const float4 v = ((const float4*)(X + (size_t)row*HID))[tid];
    float s = v.x + v.y + v.z + v.w;
    __shared__ float red[4], red2[4];
    #pragma unroll
    for (int o = 16; o; o >>= 1) s += __shfl_down_sync(0xffffffffu, s, o);
    if ((tid & 31) == 0) red[tid >> 5] = s;
    __syncthreads();
    const float m = (red[0]+red[1]+red[2]+red[3]) * (1.f/(float)HID);
    float dx = v.x - m, dy = v.y - m, dz = v.z - m, dw = v.w - m;
    float s2 = dx*dx + dy*dy + dz*dz + dw*dw;
    #pragma unroll
    for (int o = 16; o; o >>= 1) s2 += __shfl_down_sync(0xffffffffu, s2, o);
    if ((tid & 31) == 0) red2[tid >> 5] = s2;
    __syncthreads();
    const float var = (red2[0]+red2[1]+red2[2]+red2[3]) * (1.f/(float)HID);
    const float inv = rsqrtf(var + 1e-5f);
    const int c = tid * 4;
    const float4 wv = *(const float4*)(w + c);
    const float4 bv = *(const float4*)(b + c);
    __half2* Yp = (__half2*)(Y + (size_t)row*HID);
    Yp[tid*2]   = __floats2half2_rn(dx*inv*wv.x + bv.x, dy*inv*wv.y + bv.y);
    Yp[tid*2+1] = __floats2half2_rn(dz*inv*wv.z + bv.z, dw*inv*wv.w + bv.w);
}

// ---------------- attention: fp32 qkv in, half out ------------------------
__global__ void __launch_bounds__(64) attn_kernel(const float* __restrict__ qkv,
                                                  __half* __restrict__ out)
{
    const int bh = blockIdx.x;
    const int b = bh >> 3, h = bh & 7;
    const int tid = threadIdx.x;
    __shared__ float q[NPATCH][DH], k[NPATCH][DH], v[NPATCH][DH];
    __shared__ float att[NPATCH][NPATCH];

    const float* base = qkv + (size_t)(b*NPATCH) * (3*HID) + h*DH;
    for (int idx = tid; idx < NPATCH*DH; idx += 64) {
        int p = idx >> 6, d = idx & 63;
        q[p][d] = base[(size_t)p*(3*HID) + d];
        k[p][d] = base[(size_t)p*(3*HID) + HID + d];
        v[p][d] = base[(size_t)p*(3*HID) + 2*HID + d];
    }
    __syncthreads();

    for (int p = tid; p < NPATCH*NPATCH; p += 64) {
        int i = p / NPATCH, j = p % NPATCH;
        float s = 0.f;
        #pragma unroll
        for (int d = 0; d < DH; d++) s = fmaf(q[i][d], k[j][d], s);
        att[i][j] = s * 0.125f;
    }
    __syncthreads();

    if (tid < NPATCH) {
        float mx = -1e30f;
        #pragma unroll
        for (int j = 0; j < NPATCH; j++) mx = fmaxf(mx, att[tid][j]);
        float e[NPATCH], sum = 0.f;
        #pragma unroll
        for (int j = 0; j < NPATCH; j++) { e[j] = expf(att[tid][j] - mx); sum += e[j]; }
        const float r = 1.f / sum;
        #pragma unroll
        for (int j = 0; j < NPATCH; j++) att[tid][j] = e[j] * r;
    }
    __syncthreads();

    const int d = tid;
    #pragma unroll
    for (int i = 0; i < NPATCH; i++) {
        float s = 0.f;
        #pragma unroll
        for (int j = 0; j < NPATCH; j++) s = fmaf(att[i][j], v[j][d], s);
        out[(size_t)(b*NPATCH + i)*HID + h*DH + d] = __float2half_rn(s);
    }
}

// ---------------- final tiny GEMM: (4096x128)@(128x3) --------------------
__global__ void cls3_kernel(const __half* __restrict__ C2,
                            const float* __restrict__ w3,
                            const float* __restrict__ b3,
                            float* __restrict__ out)
{
    const int idx = blockIdx.x * blockDim.x + threadIdx.x;
    if (idx >= BB*NCLS) return;
    const int b = idx / NCLS, c = idx % NCLS;
    float s = b3[c];
    const __half* r = C2 + (size_t)b*128;
    #pragma unroll 8
    for (int k2 = 0; k2 < 128; k2++) s = fmaf(__half2float(r[k2]), w3[k2*NCLS + c], s);
    out[idx] = s;
}

// ---------------- host launcher ------------------------------------------
template<typename T>
static inline T* sym_addr(const void* s) {
    void* p = nullptr;
    cudaGetSymbolAddress(&p, s);
    return (T*)p;
}

template<int ACT, int RES, int OUTH>
static void launch_h(const __half* A, const __half* Bt, const float* bias,
                     const float* res, void* C, int M, int N, int K)
{
    static bool attr_done = false;
    if (!attr_done) {
        cudaFuncSetAttribute(hgemm_pipe<ACT,RES,OUTH>,
                             cudaFuncAttributeMaxDynamicSharedMemorySize, PIPE_SMEM);
        attr_done = true;
    }
    hgemm_pipe<ACT,RES,OUTH><<<dim3(N/128, M/128), 256, PIPE_SMEM>>>(A, Bt, bias, res, C, M, N, K);
}

extern "C" void kernel_launch(void* const* d_in, const int* in_sizes, int n_in,
                              void* d_out, int out_size)
{
    const float* x      = (const float*)d_in[0];
    const float* in_w   = (const float*)d_in[1];
    const float* in_b   = (const float*)d_in[2];
    const float* pe_w   = (const float*)d_in[3];
    const float* pe_b   = (const float*)d_in[4];
    const float* ln1_w  = (const float*)d_in[5];
    const float* ln1_b  = (const float*)d_in[6];
    const float* qkv_w  = (const float*)d_in[7];
    const float* qkv_b  = (const float*)d_in[8];
    const float* out_w  = (const float*)d_in[9];
    const float* out_b  = (const float*)d_in[10];
    const float* ln2_w  = (const float*)d_in[11];
    const float* ln2_b  = (const float*)d_in[12];
    const float* mlp_w1 = (const float*)d_in[13];
    const float* mlp_b1 = (const float*)d_in[14];
    const float* mlp_w2 = (const float*)d_in[15];
    const float* mlp_b2 = (const float*)d_in[16];
    const float* cls_w1 = (const float*)d_in[17];
    const float* cls_b1 = (const float*)d_in[18];
    const float* cls_w2 = (const float*)d_in[19];
    const float* cls_b2 = (const float*)d_in[20];
    const float* cls_w3 = (const float*)d_in[21];
    const float* cls_b3 = (const float*)d_in[22];

    __half* F   = sym_addr<__half>(g_feats);
    __half* Nn  = sym_addr<__half>(g_n);
    __half* O   = sym_addr<__half>(g_o);
    __half* G   = sym_addr<__half>(g_g);
    __half* Hh  = sym_addr<__half>(g_hh);
    __half* C1  = sym_addr<__half>(g_c1);
    __half* C2  = sym_addr<__half>(g_c2);
    __half* PEt = sym_addr<__half>(g_pe_wt);
    __half* QKt = sym_addr<__half>(g_qkv_wt);
    __half* OUt = sym_addr<__half>(g_out_wt);
    __half* M1t = sym_addr<__half>(g_m1_wt);
    __half* M2t = sym_addr<__half>(g_m2_wt);
    __half* C1t = sym_addr<__half>(g_c1_wt);
    __half* C2t = sym_addr<__half>(g_c2_wt);
    float*  H   = sym_addr<float>(g_h);
    float*  H2  = sym_addr<float>(g_h2);
    float*  QKV = sym_addr<float>(g_qkv);

    const dim3 tb(32, 8);
    // weight transposes: fp32 [K][N] -> half [N][Kp]
    transpose_half<<<dim3(16, 3, 1),   tb>>>(pe_w,   PEt, PDIM, HID,   PDIMP);
    transpose_half<<<dim3(48, 16, NL), tb>>>(qkv_w,  QKt, HID,  3*HID, HID);
    transpose_half<<<dim3(16, 16, NL), tb>>>(out_w,  OUt, HID,  HID,   HID);
    transpose_half<<<dim3(64, 16, NL), tb>>>(mlp_w1, M1t, HID,  MLPH,  HID);
    transpose_half<<<dim3(16, 64, NL), tb>>>(mlp_w2, M2t, MLPH, HID,   MLPH);
    transpose_half<<<dim3(16, 192, 1), tb>>>(cls_w1, C1t, HID*NPATCH, 512, HID*NPATCH);
    transpose_half<<<dim3(4, 16, 1),   tb>>>(cls_w2, C2t, 512,  128,   512);

    factors_kernel<<<BB, TT>>>(x, in_w, in_b, F);

    // patch embed: (TOK x 96) @ (512 x 96)^T -> H fp32
    launch_h<0,0,0>(F, PEt, pe_b, nullptr, H, TOK, HID, PDIMP);

    for (int i = 0; i < NL; i++) {
        ln_kernel<<<TOK, 128>>>(H, ln1_w + i*HID, ln1_b + i*HID, Nn);
        launch_h<0,0,0>(Nn, QKt + (size_t)i*3*HID*HID, qkv_b + (size_t)i*3*HID,
                        nullptr, QKV, TOK, 3*HID, HID);
        attn_kernel<<<BB*HEADS, 64>>>(QKV, O);
        launch_h<0,1,0>(O, OUt + (size_t)i*HID*HID, out_b + (size_t)i*HID,
                        H, H2, TOK, HID, HID);
        ln_kernel<<<TOK, 128>>>(H2, ln2_w + i*HID, ln2_b + i*HID, Nn);
        launch_h<1,0,1>(Nn, M1t + (size_t)i*MLPH*HID, mlp_b1 + (size_t)i*MLPH,
                        nullptr, G, TOK, MLPH, HID);
        launch_h<0,1,0>(G, M2t + (size_t)i*HID*MLPH, mlp_b2 + (size_t)i*HID,
                        H2, H, TOK, HID, MLPH);
    }

    // classifier: H fp32 -> half, then (4096 x 6144) @ (512 x 6144)^T
    f2h_kernel<<<(TOK*HID/4 + 255)/256, 256>>>((const float4*)H, (__half2*)Hh, TOK*HID/4);
    launch_h<1,0,1>(Hh, C1t, cls_b1, nullptr, C1, BB, 512, HID*NPATCH);
    launch_h<1,0,1>(C1, C2t, cls_b2, nullptr, C2, BB, 128, 512);
    cls3_kernel<<<(BB*NCLS + 127)/128, 128>>>(C2, cls_w3, cls_b3, (float*)d_out);
}

// round 16
// speedup vs baseline: 1.7125x; 1.0089x over previous
#include <cuda_runtime.h>
#include <cuda_fp16.h>
#include <math.h>
#include <stdint.h>

// ---------------- problem constants ----------------
#define BB    4096
#define TT    96
#define FRAW  5
#define TOTF  11
#define HID   512
#define NL    4
#define HEADS 8
#define DH    64
#define PATCH 8
#define NPATCH 12
#define PDIM  88
#define PDIMP 96
#define TOK   (BB*NPATCH)   // 49152
#define MLPH  2048
#define NCLS  3

// ---------------- scratch (static device, no allocation) ----------------
__device__ __align__(256) __half g_feats[(size_t)TOK*PDIMP];
__device__ __align__(256) __half g_n   [(size_t)TOK*HID];
__device__ __align__(256) __half g_qkvh[(size_t)TOK*3*HID];
__device__ __align__(256) __half g_o   [(size_t)TOK*HID];
__device__ __align__(256) __half g_g   [(size_t)TOK*MLPH];
__device__ __align__(256) __half g_hh  [(size_t)TOK*HID];
__device__ __align__(256) __half g_c1  [(size_t)BB*512];
__device__ __align__(256) __half g_c2  [(size_t)BB*128];
__device__ __align__(256) __half g_pe_wt [(size_t)HID*PDIMP];
__device__ __align__(256) __half g_qkv_wt[(size_t)NL*3*HID*HID];
__device__ __align__(256) __half g_out_wt[(size_t)NL*HID*HID];
__device__ __align__(256) __half g_m1_wt [(size_t)NL*MLPH*HID];
__device__ __align__(256) __half g_m2_wt [(size_t)NL*HID*MLPH];
__device__ __align__(256) __half g_c1_wt [(size_t)512*HID*NPATCH];
__device__ __align__(256) __half g_c2_wt [(size_t)128*512];
// fp32 buffers
__device__ float g_h  [(size_t)TOK*HID];
__device__ float g_h2 [(size_t)TOK*HID];

__device__ __forceinline__ float gelu_f(float x) {
    return 0.5f * x * (1.f + erff(x * 0.7071067811865476f));
}
__device__ __forceinline__ uint32_t s2u(const void* p) {
    uint32_t a;
    asm("{ .reg .u64 t; cvta.to.shared.u64 t, %1; cvt.u32.u64 %0, t; }" : "=r"(a) : "l"(p));
    return a;
}
__device__ __forceinline__ void mma_f16(float c[4], const uint32_t a[4], const uint32_t b[2]) {
    asm volatile(
        "mma.sync.aligned.m16n8k16.row.col.f32.f16.f16.f32 "
        "{%0,%1,%2,%3}, {%4,%5,%6,%7}, {%8,%9}, {%0,%1,%2,%3};"
        : "+f"(c[0]), "+f"(c[1]), "+f"(c[2]), "+f"(c[3])
        : "r"(a[0]), "r"(a[1]), "r"(a[2]), "r"(a[3]), "r"(b[0]), "r"(b[1]));
}

// ---------------- fused weight transpose: 7 jobs, one launch --------------
// fp32 [K][N] (xz jobs stacked in z) -> half [N][Kp], zero-padded K
struct TJob { const float* src; __half* dst; int K, N, Kp; };
struct TJobs { TJob j[7]; };

// per-job grid dims (constexpr): gx=ceil(N/32), gy=ceil(K/32), gz
#define TJ_GX(N_) (((N_)+31)/32)
#define TJ_GY(K_) (((K_)+31)/32)
// jobs: pe(88,512,96,z1) qkv(512,1536,512,z4) out(512,512,512,z4)
//       m1(512,2048,512,z4) m2(2048,512,2048,z4) c1(6144,512,6144,z1) c2(512,128,512,z1)
__constant__ int c_tj_meta[7][4] = {
    {TJ_GX(512),  TJ_GY(88),   1, 0},
    {TJ_GX(1536), TJ_GY(512),  4, 0},
    {TJ_GX(512),  TJ_GY(512),  4, 0},
    {TJ_GX(2048), TJ_GY(512),  4, 0},
    {TJ_GX(512),  TJ_GY(2048), 4, 0},
    {TJ_GX(512),  TJ_GY(6144), 1, 0},
    {TJ_GX(128),  TJ_GY(512),  1, 0},
};

__global__ void transpose_all(TJobs jobs)
{
    __shared__ float t[32][33];
    // locate job
    int blk = blockIdx.x;
    int ji = 0;
    #pragma unroll
    for (int i = 0; i < 7; i++) {
        const int cnt = c_tj_meta[i][0] * c_tj_meta[i][1] * c_tj_meta[i][2];
        if (blk >= cnt && ji == i) { blk -= cnt; ji = i + 1; }
    }
    const TJob jb = jobs.j[ji];
    const int gx = c_tj_meta[ji][0];
    const int gy = c_tj_meta[ji][1];
    const int bx = blk % gx;
    const int rem = blk / gx;
    const int by = rem % gy;
    const int bz = rem / gy;

    const float* src = jb.src + (size_t)bz * jb.K * jb.N;
    __half* dst = jb.dst + (size_t)bz * jb.N * jb.Kp;
    const int kBase = by*32, nBase = bx*32;
    for (int i = threadIdx.y; i < 32; i += 8) {
        int k = kBase + i, n = nBase + threadIdx.x;
        t[i][threadIdx.x] = (k < jb.K && n < jb.N) ? src[(size_t)k*jb.N + n] : 0.f;
    }
    __syncthreads();
    for (int i = threadIdx.y; i < 32; i += 8) {
        int n = nBase + i, k = kBase + threadIdx.x;
        if (n < jb.N && k < jb.Kp) dst[(size_t)n*jb.Kp + k] = __float2half_rn(t[threadIdx.x][i]);
    }
}
#define TJ_TOTAL_BLOCKS (TJ_GX(512)*TJ_GY(88) + TJ_GX(1536)*TJ_GY(512)*4 + \
    TJ_GX(512)*TJ_GY(512)*4 + TJ_GX(2048)*TJ_GY(512)*4 + TJ_GX(512)*TJ_GY(2048)*4 + \
    TJ_GX(512)*TJ_GY(6144) + TJ_GX(128)*TJ_GY(512))

// ---------------- pipelined fp16 tensor GEMM (NT) -------------------------
// C = act(A@Bt^T + bias [+res]); A [M][K] half, Bt [N][K] half.
// OUTH: 0=fp32 out, 1=half out, 2=fp32 out + half copy to C2h.
#define SAH 40
#define STG_HF (2*128*SAH)
#define STG_BYTES (STG_HF*2)
#define NSTAGE 3
#define PIPE_SMEM (NSTAGE*STG_BYTES)

template<int ACT, int RES, int OUTH>
__global__ void __launch_bounds__(256, 2) hgemm_pipe(
    const __half* __restrict__ A, const __half* __restrict__ Bt,
    const float* __restrict__ bias, const float* __restrict__ res,
    void* __restrict__ Cv, __half* __restrict__ C2h, int M, int N, int K)
{
    extern __shared__ __half hsm[];
    const int tid  = threadIdx.x;
    const int lane = tid & 31;
    const int wid  = tid >> 5;
    const int g    = lane >> 2;
    const int t4   = lane & 3;
    const int wm   = wid & 3;
    const int wn   = wid >> 2;
    const int mBase = wm * 32;
    const int nBase = wn * 64;

    const __half* Ab = A  + (size_t)blockIdx.y * 128 * K;
    const __half* Bb = Bt + (size_t)blockIdx.x * 128 * K;
    const int nk = K >> 5;

    const uint32_t smemBase = s2u(hsm);

    const int r0c = tid >> 2,         q0 = (tid & 3) * 8;
    const int r1c = (tid + 256) >> 2, q1 = (tid & 3) * 8;

// macro-local kbi (NOT kb): must capture loop var, not shadow it
#define ISSUE(kb_) do {                                                            \
    const int kbi = (kb_);                                                         \
    if (kbi < nk) {                                                                \
        const int k0 = kbi << 5;                                                   \
        const uint32_t sA = smemBase + (uint32_t)((kbi % NSTAGE) * STG_BYTES);     \
        const uint32_t sB = sA + 128*SAH*2;                                        \
        asm volatile("cp.async.cg.shared.global [%0], [%1], 16;" ::                \
            "r"(sA + (uint32_t)(r0c*SAH + q0)*2), "l"(Ab + (size_t)r0c*K + k0 + q0)); \
        asm volatile("cp.async.cg.shared.global [%0], [%1], 16;" ::                \
            "r"(sA + (uint32_t)(r1c*SAH + q1)*2), "l"(Ab + (size_t)r1c*K + k0 + q1)); \
        asm volatile("cp.async.cg.shared.global [%0], [%1], 16;" ::                \
            "r"(sB + (uint32_t)(r0c*SAH + q0)*2), "l"(Bb + (size_t)r0c*K + k0 + q0)); \
        asm volatile("cp.async.cg.shared.global [%0], [%1], 16;" ::                \
            "r"(sB + (uint32_t)(r1c*SAH + q1)*2), "l"(Bb + (size_t)r1c*K + k0 + q1)); \
    }                                                                              \
    asm volatile("cp.async.commit_group;" ::: "memory");                           \
} while (0)

    ISSUE(0);
    ISSUE(1);

    float acc[2][8][4] = {};

    for (int kb = 0; kb < nk; kb++) {
        asm volatile("cp.async.wait_group 1;" ::: "memory");
        __syncthreads();
        ISSUE(kb + 2);

        const __half* As = hsm + (kb % NSTAGE) * STG_HF;
        const __half* Bs = As + 128*SAH;

        #pragma unroll
        for (int kk = 0; kk < 32; kk += 16) {
            uint32_t af[2][4];
            #pragma unroll
            for (int mi = 0; mi < 2; mi++) {
                const int m0 = mBase + mi*16;
                af[mi][0] = *(const uint32_t*)&As[(m0 + g    )*SAH + kk + 2*t4    ];
                af[mi][1] = *(const uint32_t*)&As[(m0 + g + 8)*SAH + kk + 2*t4    ];
                af[mi][2] = *(const uint32_t*)&As[(m0 + g    )*SAH + kk + 2*t4 + 8];
                af[mi][3] = *(const uint32_t*)&As[(m0 + g + 8)*SAH + kk + 2*t4 + 8];
            }
            uint32_t bf[8][2];
            #pragma unroll
            for (int ni = 0; ni < 8; ni++) {
                const int n0 = nBase + ni*8 + g;
                bf[ni][0] = *(const uint32_t*)&Bs[n0*SAH + kk + 2*t4    ];
                bf[ni][1] = *(const uint32_t*)&Bs[n0*SAH + kk + 2*t4 + 8];
            }
            #pragma unroll
            for (int mi = 0; mi < 2; mi++)
                #pragma unroll
                for (int ni = 0; ni < 8; ni++)
                    mma_f16(acc[mi][ni], af[mi], bf[ni]);
        }
    }
#undef ISSUE

    // ---- epilogue ----
    const int rowTile = blockIdx.y * 128;
    const int colTile = blockIdx.x * 128;
    #pragma unroll
    for (int mi = 0; mi < 2; mi++) {
        const int r0 = rowTile + mBase + mi*16 + g;
        #pragma unroll
        for (int ni = 0; ni < 8; ni++) {
            const int c = colTile + nBase + ni*8 + t4*2;
            const float2 bz = *(const float2*)(bias + c);
            float v0 = acc[mi][ni][0] + bz.x;
            float v1 = acc[mi][ni][1] + bz.y;
            float v2 = acc[mi][ni][2] + bz.x;
            float v3 = acc[mi][ni][3] + bz.y;
            const size_t off0 = (size_t)r0 * N + c;
            const size_t off1 = (size_t)(r0 + 8) * N + c;
            if (RES) {
                const float2 ra = *(const float2*)(res + off0);
                const float2 rb = *(const float2*)(res + off1);
                v0 += ra.x; v1 += ra.y; v2 += rb.x; v3 += rb.y;
            }
            if (ACT == 1) {
                v0 = gelu_f(v0); v1 = gelu_f(v1);
                v2 = gelu_f(v2); v3 = gelu_f(v3);
            }
            if (OUTH == 1) {
                __half* C = (__half*)Cv;
                *(__half2*)(C + off0) = __floats2half2_rn(v0, v1);
                *(__half2*)(C + off1) = __floats2half2_rn(v2, v3);
            } else {
                float* C = (float*)Cv;
                *(float2*)(C + off0) = make_float2(v0, v1);
                *(float2*)(C + off1) = make_float2(v2, v3);
                if (OUTH == 2) {
                    *(__half2*)(C2h + off0) = __floats2half2_rn(v0, v1);
                    *(__half2*)(C2h + off1) = __floats2half2_rn(v2, v3);
                }
            }
        }
    }
}

// ---------------- stage 1: factor engineering + time-norm (half out) -----
__global__ void factors_kernel(const float* __restrict__ x,
                               const float* __restrict__ in_w,
                               const float* __restrict__ in_b,
                               __half* __restrict__ feats)
{
    __shared__ float cl[TT], vol[TT];
    __shared__ float sf[TT][TOTF];
    __shared__ float mean_s[TOTF], inv_s[TOTF];
    const int b = blockIdx.x;
    const int t = threadIdx.x;
    const float* xb = x + (size_t)b * TT * FRAW;

    if (t < TT) { cl[t] = xb[t*FRAW + 3]; vol[t] = xb[t*FRAW + 4]; }
    __syncthreads();

    if (t < TT) {
        const float a13 = 2.f/13.f, a27 = 2.f/27.f, a14 = 1.f/14.f;
        float e13 = cl[0], e27 = cl[0];
        float eg = 0.f, el = 0.f;
        for (int j = 1; j <= t; j++) {
            float c = cl[j];
            e13 = a13*c + (1.f - a13)*e13;
            e27 = a27*c + (1.f - a27)*e27;
            float d = c - cl[j-1];
            float gg = fmaxf(d, 0.f);
            float ll = -fminf(d, 0.f);
            eg = a14*gg + (1.f - a14)*eg;
            el = a14*ll + (1.f - a14)*el;
        }
        float macd = e13 - e27;
        float rs  = eg / (el + 1e-10f);
        float rsi = (100.f - 100.f/(1.f + rs)) * 0.01f;

        float bb = 0.f;
        if (t >= 19) {
            float s = 0.f, s2 = 0.f;
            for (int j = t-19; j <= t; j++) { float c = cl[j]; s += c; s2 += c*c; }
            float m  = s * 0.05f;
            float sq = s2 * 0.05f;
            float sd = sqrtf(fmaxf(sq - m*m, 0.f));
            bb = 4.f * sd / (m + 1e-8f);
        }

        float lr = 0.f, lv = 0.f;
        float svt = vol[t] > 0.f ? vol[t] : 1.f;
        if (t >= 1) {
            float pc = fmaxf(cl[t-1], 1e-8f);
            lr = logf(fmaxf(cl[t], 1e-8f) / pc);
            float svp = vol[t-1] > 0.f ? vol[t-1] : 1.f;
            lv = logf(svt / (svp + 1e-8f));
        }

        float vmr = 1.f;
        if (t >= 19) {
            float s = 0.f;
            for (int j = t-19; j <= t; j++) { float v2 = vol[j] > 0.f ? vol[j] : 1.f; s += v2; }
            vmr = svt / (s * 0.05f + 1e-8f);
        }

        float f6[6] = {macd, rsi, bb, lr, lv, vmr};
        #pragma unroll
        for (int f = 0; f < FRAW; f++) sf[t][f] = xb[t*FRAW + f];
        #pragma unroll
        for (int f = 0; f < 6; f++) {
            float v = f6[f];
            if (!isfinite(v)) v = 0.f;
            sf[t][FRAW + f] = v;
        }
    }
    __syncthreads();

    if (t < TOTF) {
        float s = 0.f;
        for (int j = 0; j < TT; j++) s += sf[j][t];
        mean_s[t] = s / (float)TT;
    }
    __syncthreads();
    if (t < TOTF) {
        float m = mean_s[t], s = 0.f;
        for (int j = 0; j < TT; j++) { float d = sf[j][t] - m; s += d*d; }
        inv_s[t] = rsqrtf(s / (float)TT + 1e-5f);
    }
    __syncthreads();

    if (t < TT) {
        const int token = b*NPATCH + (t / PATCH);
        __half* o = feats + (size_t)token*PDIMP + (t % PATCH)*TOTF;
        #pragma unroll
        for (int f = 0; f < TOTF; f++)
            o[f] = __float2half_rn((sf[t][f] - mean_s[f]) * inv_s[f] * in_w[f] + in_b[f]);
    }
    if (t < NPATCH) {
        __half* z = feats + (size_t)(b*NPATCH + t)*PDIMP + PDIM;
        #pragma unroll
        for (int i = 0; i < PDIMP - PDIM; i++) z[i] = __float2half_rn(0.f);
    }
}

// ---------------- LayerNorm: fp32 in, half out ----------------------------
__global__ void __launch_bounds__(128) ln_kernel(const float* __restrict__ X,
                                                 const float* __restrict__ w,
                                                 const float* __restrict__ b,
                                                 __half* __restrict__ Y)
{
    const int row = blockIdx.x;
    const int tid = threadIdx.x;
    const float4 v = ((const float4*)(X + (size_t)row*HID))[tid];
    float s = v.x + v.y + v.z + v.w;
    __shared__ float red[4], red2[4];
    #pragma unroll
    for (int o = 16; o; o >>= 1) s += __shfl_down_sync(0xffffffffu, s, o);
    if ((tid & 31) == 0) red[tid >> 5] = s;
    __syncthreads();
    const float m = (red[0]+red[1]+red[2]+red[3]) * (1.f/(float)HID);
    float dx = v.x - m, dy = v.y - m, dz = v.z - m, dw = v.w - m;
    float s2 = dx*dx + dy*dy + dz*dz + dw*dw;
    #pragma unroll
    for (int o = 16; o; o >>= 1) s2 += __shfl_down_sync(0xffffffffu, s2, o);
    if ((tid & 31) == 0) red2[tid >> 5] = s2;
    __syncthreads();
    const float var = (red2[0]+red2[1]+red2[2]+red2[3]) * (1.f/(float)HID);
    const float inv = rsqrtf(var + 1e-5f);
    const int c = tid * 4;
    const float4 wv = *(const float4*)(w + c);
    const float4 bv = *(const float4*)(b + c);
    __half2* Yp = (__half2*)(Y + (size_t)row*HID);
    Yp[tid*2]   = __floats2half2_rn(dx*inv*wv.x + bv.x, dy*inv*wv.y + bv.y);
    Yp[tid*2+1] = __floats2half2_rn(dz*inv*wv.z + bv.z, dw*inv*wv.w + bv.w);
}

// ---------------- attention: half qkv in, half out ------------------------
__global__ void __launch_bounds__(64) attn_kernel(const __half* __restrict__ qkv,
                                                  __half* __restrict__ out)
{
    const int bh = blockIdx.x;
    const int b = bh >> 3, h = bh & 7;
    const int tid = threadIdx.x;
    __shared__ float q[NPATCH][DH], k[NPATCH][DH], v[NPATCH][DH];
    __shared__ float att[NPATCH][NPATCH];

    const __half* base = qkv + (size_t)(b*NPATCH) * (3*HID) + h*DH;
    // 64 threads x 2 half2 per row-segment: NPATCH*DH/2 = 384 half2 per matrix
    for (int idx = tid; idx < NPATCH*DH/2; idx += 64) {
        int p = idx / (DH/2), d2 = idx % (DH/2);
        const __half2 hq = *(const __half2*)(base + (size_t)p*(3*HID)            + d2*2);
        const __half2 hk = *(const __half2*)(base + (size_t)p*(3*HID) + HID      + d2*2);
        const __half2 hv = *(const __half2*)(base + (size_t)p*(3*HID) + 2*HID    + d2*2);
        const float2 fq = __half22float2(hq);
        const float2 fk = __half22float2(hk);
        const float2 fv = __half22float2(hv);
        q[p][d2*2] = fq.x; q[p][d2*2+1] = fq.y;
        k[p][d2*2] = fk.x; k[p][d2*2+1] = fk.y;
        v[p][d2*2] = fv.x; v[p][d2*2+1] = fv.y;
    }
    __syncthreads();

    for (int p = tid; p < NPATCH*NPATCH; p += 64) {
        int i = p / NPATCH, j = p % NPATCH;
        float s = 0.f;
        #pragma unroll
        for (int d = 0; d < DH; d++) s = fmaf(q[i][d], k[j][d], s);
        att[i][j] = s * 0.125f;
    }
    __syncthreads();

    if (tid < NPATCH) {
        float mx = -1e30f;
        #pragma unroll
        for (int j = 0; j < NPATCH; j++) mx = fmaxf(mx, att[tid][j]);
        float e[NPATCH], sum = 0.f;
        #pragma unroll
        for (int j = 0; j < NPATCH; j++) { e[j] = expf(att[tid][j] - mx); sum += e[j]; }
        const float r = 1.f / sum;
        #pragma unroll
        for (int j = 0; j < NPATCH; j++) att[tid][j] = e[j] * r;
    }
    __syncthreads();

    const int d = tid;
    #pragma unroll
    for (int i = 0; i < NPATCH; i++) {
        float s = 0.f;
        #pragma unroll
        for (int j = 0; j < NPATCH; j++) s = fmaf(att[i][j], v[j][d], s);
        out[(size_t)(b*NPATCH + i)*HID + h*DH + d] = __float2half_rn(s);
    }
}

// ---------------- final tiny GEMM: (4096x128)@(128x3) --------------------
__global__ void cls3_kernel(const __half* __restrict__ C2,
                            const float* __restrict__ w3,
                            const float* __restrict__ b3,
                            float* __restrict__ out)
{
    const int idx = blockIdx.x * blockDim.x + threadIdx.x;
    if (idx >= BB*NCLS) return;
    const int b = idx / NCLS, c = idx % NCLS;
    float s = b3[c];
    const __half* r = C2 + (size_t)b*128;
    #pragma unroll 8
    for (int k2 = 0; k2 < 128; k2++) s = fmaf(__half2float(r[k2]), w3[k2*NCLS + c], s);
    out[idx] = s;
}

// ---------------- host launcher ------------------------------------------
template<typename T>
static inline T* sym_addr(const void* s) {
    void* p = nullptr;
    cudaGetSymbolAddress(&p, s);
    return (T*)p;
}

template<int ACT, int RES, int OUTH>
static void launch_h(const __half* A, const __half* Bt, const float* bias,
                     const float* res, void* C, __half* C2h, int M, int N, int K)
{
    static bool attr_done = false;
    if (!attr_done) {
        cudaFuncSetAttribute(hgemm_pipe<ACT,RES,OUTH>,
                             cudaFuncAttributeMaxDynamicSharedMemorySize, PIPE_SMEM);
        attr_done = true;
    }
    hgemm_pipe<ACT,RES,OUTH><<<dim3(N/128, M/128), 256, PIPE_SMEM>>>(A, Bt, bias, res, C, C2h, M, N, K);
}

extern "C" void kernel_launch(void* const* d_in, const int* in_sizes, int n_in,
                              void* d_out, int out_size)
{
    const float* x      = (const float*)d_in[0];
    const float* in_w   = (const float*)d_in[1];
    const float* in_b   = (const float*)d_in[2];
    const float* pe_w   = (const float*)d_in[3];
    const float* pe_b   = (const float*)d_in[4];
    const float* ln1_w  = (const float*)d_in[5];
    const float* ln1_b  = (const float*)d_in[6];
    const float* qkv_w  = (const float*)d_in[7];
    const float* qkv_b  = (const float*)d_in[8];
    const float* out_w  = (const float*)d_in[9];
    const float* out_b  = (const float*)d_in[10];
    const float* ln2_w  = (const float*)d_in[11];
    const float* ln2_b  = (const float*)d_in[12];
    const float* mlp_w1 = (const float*)d_in[13];
    const float* mlp_b1 = (const float*)d_in[14];
    const float* mlp_w2 = (const float*)d_in[15];
    const float* mlp_b2 = (const float*)d_in[16];
    const float* cls_w1 = (const float*)d_in[17];
    const float* cls_b1 = (const float*)d_in[18];
    const float* cls_w2 = (const float*)d_in[19];
    const float* cls_b2 = (const float*)d_in[20];
    const float* cls_w3 = (const float*)d_in[21];
    const float* cls_b3 = (const float*)d_in[22];

    __half* F    = sym_addr<__half>(g_feats);
    __half* Nn   = sym_addr<__half>(g_n);
    __half* QKVh = sym_addr<__half>(g_qkvh);
    __half* O    = sym_addr<__half>(g_o);
    __half* G    = sym_addr<__half>(g_g);
    __half* Hh   = sym_addr<__half>(g_hh);
    __half* C1   = sym_addr<__half>(g_c1);
    __half* C2   = sym_addr<__half>(g_c2);
    __half* PEt  = sym_addr<__half>(g_pe_wt);
    __half* QKt  = sym_addr<__half>(g_qkv_wt);
    __half* OUt  = sym_addr<__half>(g_out_wt);
    __half* M1t  = sym_addr<__half>(g_m1_wt);
    __half* M2t  = sym_addr<__half>(g_m2_wt);
    __half* C1t  = sym_addr<__half>(g_c1_wt);
    __half* C2t  = sym_addr<__half>(g_c2_wt);
    float*  H    = sym_addr<float>(g_h);
    float*  H2   = sym_addr<float>(g_h2);

    // fused weight transpose (all 7 jobs, one launch)
    TJobs jobs;
    jobs.j[0] = { pe_w,   PEt, PDIM, HID,   PDIMP };
    jobs.j[1] = { qkv_w,  QKt, HID,  3*HID, HID   };
    jobs.j[2] = { out_w,  OUt, HID,  HID,   HID   };
    jobs.j[3] = { mlp_w1, M1t, HID,  MLPH,  HID   };
    jobs.j[4] = { mlp_w2, M2t, MLPH, HID,   MLPH  };
    jobs.j[5] = { cls_w1, C1t, HID*NPATCH, 512, HID*NPATCH };
    jobs.j[6] = { cls_w2, C2t, 512,  128,   512   };
    transpose_all<<<TJ_TOTAL_BLOCKS, dim3(32, 8)>>>(jobs);

    factors_kernel<<<BB, TT>>>(x, in_w, in_b, F);

    // patch embed: (TOK x 96) @ (512 x 96)^T -> H fp32
    launch_h<0,0,0>(F, PEt, pe_b, nullptr, H, nullptr, TOK, HID, PDIMP);

    for (int i = 0; i < NL; i++) {
        ln_kernel<<<TOK, 128>>>(H, ln1_w + i*HID, ln1_b + i*HID, Nn);
        launch_h<0,0,1>(Nn, QKt + (size_t)i*3*HID*HID, qkv_b + (size_t)i*3*HID,
                        nullptr, QKVh, nullptr, TOK, 3*HID, HID);
        attn_kernel<<<BB*HEADS, 64>>>(QKVh, O);
        launch_h<0,1,0>(O, OUt + (size_t)i*HID*HID, out_b + (size_t)i*HID,
                        H, H2, nullptr, TOK, HID, HID);
        ln_kernel<<<TOK, 128>>>(H2, ln2_w + i*HID, ln2_b + i*HID, Nn);
        launch_h<1,0,1>(Nn, M1t + (size_t)i*MLPH*HID, mlp_b1 + (size_t)i*MLPH,
                        nullptr, G, nullptr, TOK, MLPH, HID);
        if (i < NL-1) {
            launch_h<0,1,0>(G, M2t + (size_t)i*HID*MLPH, mlp_b2 + (size_t)i*HID,
                            H2, H, nullptr, TOK, HID, MLPH);
        } else {
            // final layer: dual output (fp32 H for nothing downstream, half Hh for cls1)
            launch_h<0,1,2>(G, M2t + (size_t)i*HID*MLPH, mlp_b2 + (size_t)i*HID,
                            H2, H, Hh, TOK, HID, MLPH);
        }
    }

    // classifier: Hh viewed as (4096 x 6144) @ (512 x 6144)^T
    launch_h<1,0,1>(Hh, C1t, cls_b1, nullptr, C1, nullptr, BB, 512, HID*NPATCH);
    launch_h<1,0,1>(C1, C2t, cls_b2, nullptr, C2, nullptr, BB, 128, 512);
    cls3_kernel<<<(BB*NCLS + 127)/128, 128>>>(C2, cls_w3, cls_b3, (float*)d_out);
}

// round 17
// speedup vs baseline: 1.8470x; 1.0786x over previous
#include <cuda_runtime.h>
#include <cuda_fp16.h>
#include <math.h>
#include <stdint.h>

// ---------------- problem constants ----------------
#define BB    4096
#define TT    96
#define FRAW  5
#define TOTF  11
#define HID   512
#define NL    4
#define HEADS 8
#define DH    64
#define PATCH 8
#define NPATCH 12
#define PDIM  88
#define PDIMP 96
#define TOK   (BB*NPATCH)   // 49152
#define MLPH  2048
#define NCLS  3

// ---------------- scratch (static device, no allocation) ----------------
__device__ __align__(256) __half g_feats[(size_t)TOK*PDIMP];
__device__ __align__(256) __half g_n   [(size_t)TOK*HID];
__device__ __align__(256) __half g_qkvh[(size_t)TOK*3*HID];
__device__ __align__(256) __half g_o   [(size_t)TOK*HID];
__device__ __align__(256) __half g_g   [(size_t)TOK*MLPH];
__device__ __align__(256) __half g_hh  [(size_t)TOK*HID];
__device__ __align__(256) __half g_c1  [(size_t)BB*512];
__device__ __align__(256) __half g_c2  [(size_t)BB*128];
__device__ __align__(256) __half g_pe_wt [(size_t)HID*PDIMP];
__device__ __align__(256) __half g_qkv_wt[(size_t)NL*3*HID*HID];
__device__ __align__(256) __half g_out_wt[(size_t)NL*HID*HID];
__device__ __align__(256) __half g_m1_wt [(size_t)NL*MLPH*HID];
__device__ __align__(256) __half g_m2_wt [(size_t)NL*HID*MLPH];
__device__ __align__(256) __half g_c1_wt [(size_t)512*HID*NPATCH];
__device__ __align__(256) __half g_c2_wt [(size_t)128*512];
// fp32 buffers
__device__ float g_h  [(size_t)TOK*HID];
__device__ float g_h2 [(size_t)TOK*HID];

__device__ __forceinline__ float gelu_f(float x) {
    return 0.5f * x * (1.f + erff(x * 0.7071067811865476f));
}
__device__ __forceinline__ uint32_t s2u(const void* p) {
    uint32_t a;
    asm("{ .reg .u64 t; cvta.to.shared.u64 t, %1; cvt.u32.u64 %0, t; }" : "=r"(a) : "l"(p));
    return a;
}
__device__ __forceinline__ void mma_f16(float c[4], const uint32_t a[4], const uint32_t b[2]) {
    asm volatile(
        "mma.sync.aligned.m16n8k16.row.col.f32.f16.f16.f32 "
        "{%0,%1,%2,%3}, {%4,%5,%6,%7}, {%8,%9}, {%0,%1,%2,%3};"
        : "+f"(c[0]), "+f"(c[1]), "+f"(c[2]), "+f"(c[3])
        : "r"(a[0]), "r"(a[1]), "r"(a[2]), "r"(a[3]), "r"(b[0]), "r"(b[1]));
}
__device__ __forceinline__ void ldsm_x4(uint32_t& r0, uint32_t& r1, uint32_t& r2, uint32_t& r3,
                                        uint32_t addr) {
    asm volatile("ldmatrix.sync.aligned.m8n8.x4.shared.b16 {%0,%1,%2,%3}, [%4];"
                 : "=r"(r0), "=r"(r1), "=r"(r2), "=r"(r3) : "r"(addr));
}

// ---------------- fused weight transpose: 7 jobs, one launch --------------
struct TJob { const float* src; __half* dst; int K, N, Kp; };
struct TJobs { TJob j[7]; };

#define TJ_GX(N_) (((N_)+31)/32)
#define TJ_GY(K_) (((K_)+31)/32)
__constant__ int c_tj_meta[7][4] = {
    {TJ_GX(512),  TJ_GY(88),   1, 0},
    {TJ_GX(1536), TJ_GY(512),  4, 0},
    {TJ_GX(512),  TJ_GY(512),  4, 0},
    {TJ_GX(2048), TJ_GY(512),  4, 0},
    {TJ_GX(512),  TJ_GY(2048), 4, 0},
    {TJ_GX(512),  TJ_GY(6144), 1, 0},
    {TJ_GX(128),  TJ_GY(512),  1, 0},
};

__global__ void transpose_all(TJobs jobs)
{
    __shared__ float t[32][33];
    int blk = blockIdx.x;
    int ji = 0;
    #pragma unroll
    for (int i = 0; i < 7; i++) {
        const int cnt = c_tj_meta[i][0] * c_tj_meta[i][1] * c_tj_meta[i][2];
        if (blk >= cnt && ji == i) { blk -= cnt; ji = i + 1; }
    }
    const TJob jb = jobs.j[ji];
    const int gx = c_tj_meta[ji][0];
    const int gy = c_tj_meta[ji][1];
    const int bx = blk % gx;
    const int rem = blk / gx;
    const int by = rem % gy;
    const int bz = rem / gy;

    const float* src = jb.src + (size_t)bz * jb.K * jb.N;
    __half* dst = jb.dst + (size_t)bz * jb.N * jb.Kp;
    const int kBase = by*32, nBase = bx*32;
    for (int i = threadIdx.y; i < 32; i += 8) {
        int k = kBase + i, n = nBase + threadIdx.x;
        t[i][threadIdx.x] = (k < jb.K && n < jb.N) ? src[(size_t)k*jb.N + n] : 0.f;
    }
    __syncthreads();
    for (int i = threadIdx.y; i < 32; i += 8) {
        int n = nBase + i, k = kBase + threadIdx.x;
        if (n < jb.N && k < jb.Kp) dst[(size_t)n*jb.Kp + k] = __float2half_rn(t[threadIdx.x][i]);
    }
}
#define TJ_TOTAL_BLOCKS (TJ_GX(512)*TJ_GY(88) + TJ_GX(1536)*TJ_GY(512)*4 + \
    TJ_GX(512)*TJ_GY(512)*4 + TJ_GX(2048)*TJ_GY(512)*4 + TJ_GX(512)*TJ_GY(2048)*4 + \
    TJ_GX(512)*TJ_GY(6144) + TJ_GX(128)*TJ_GY(512))

// ---------------- pipelined fp16 tensor GEMM (NT, ldmatrix) ---------------
// C = act(A@Bt^T + bias [+res]); A [M][K] half, Bt [N][K] half.
// OUTH: 0=fp32 out, 1=half out, 2=fp32 out + half copy to C2h.
#define SAH 40
#define STG_HF (2*128*SAH)
#define STG_BYTES (STG_HF*2)
#define NSTAGE 3
#define PIPE_SMEM (NSTAGE*STG_BYTES)

template<int ACT, int RES, int OUTH>
__global__ void __launch_bounds__(256, 2) hgemm_pipe(
    const __half* __restrict__ A, const __half* __restrict__ Bt,
    const float* __restrict__ bias, const float* __restrict__ res,
    void* __restrict__ Cv, __half* __restrict__ C2h, int M, int N, int K)
{
    extern __shared__ __half hsm[];
    const int tid  = threadIdx.x;
    const int lane = tid & 31;
    const int wid  = tid >> 5;
    const int g    = lane >> 2;
    const int t4   = lane & 3;
    const int wm   = wid & 3;
    const int wn   = wid >> 2;
    const int mBase = wm * 32;
    const int nBase = wn * 64;

    // ldmatrix lane->row mappings (loop-invariant)
    const int lj  = lane >> 3, lr = lane & 7;
    const int mLane  = (lj & 1)*8 + lr;   // A: matrices {m, m+8} x {k, k+8}
    const int kaLane = (lj >> 1)*8;
    const int nLane  = (lj >> 1)*8 + lr;  // B: matrices {k, k+8} x {n, n+8}
    const int kbLane = (lj & 1)*8;

    const __half* Ab = A  + (size_t)blockIdx.y * 128 * K;
    const __half* Bb = Bt + (size_t)blockIdx.x * 128 * K;
    const int nk = K >> 5;

    const uint32_t smemBase = s2u(hsm);

    const int r0c = tid >> 2,         q0 = (tid & 3) * 8;
    const int r1c = (tid + 256) >> 2, q1 = (tid & 3) * 8;

// macro-local kbi (NOT kb): must capture loop var, not shadow it
#define ISSUE(kb_) do {                                                            \
    const int kbi = (kb_);                                                         \
    if (kbi < nk) {                                                                \
        const int k0 = kbi << 5;                                                   \
        const uint32_t sA = smemBase + (uint32_t)((kbi % NSTAGE) * STG_BYTES);     \
        const uint32_t sB = sA + 128*SAH*2;                                        \
        asm volatile("cp.async.cg.shared.global [%0], [%1], 16;" ::                \
            "r"(sA + (uint32_t)(r0c*SAH + q0)*2), "l"(Ab + (size_t)r0c*K + k0 + q0)); \
        asm volatile("cp.async.cg.shared.global [%0], [%1], 16;" ::                \
            "r"(sA + (uint32_t)(r1c*SAH + q1)*2), "l"(Ab + (size_t)r1c*K + k0 + q1)); \
        asm volatile("cp.async.cg.shared.global [%0], [%1], 16;" ::                \
            "r"(sB + (uint32_t)(r0c*SAH + q0)*2), "l"(Bb + (size_t)r0c*K + k0 + q0)); \
        asm volatile("cp.async.cg.shared.global [%0], [%1], 16;" ::                \
            "r"(sB + (uint32_t)(r1c*SAH + q1)*2), "l"(Bb + (size_t)r1c*K + k0 + q1)); \
    }                                                                              \
    asm volatile("cp.async.commit_group;" ::: "memory");                           \
} while (0)

    ISSUE(0);
    ISSUE(1);

    float acc[2][8][4] = {};

    for (int kb = 0; kb < nk; kb++) {
        asm volatile("cp.async.wait_group 1;" ::: "memory");
        __syncthreads();
        ISSUE(kb + 2);

        const uint32_t sA = smemBase + (uint32_t)((kb % NSTAGE) * STG_BYTES);
        const uint32_t sB = sA + 128*SAH*2;

        #pragma unroll
        for (int kk = 0; kk < 32; kk += 16) {
            uint32_t af[2][4];
            #pragma unroll
            for (int mi = 0; mi < 2; mi++)
                ldsm_x4(af[mi][0], af[mi][1], af[mi][2], af[mi][3],
                        sA + (uint32_t)((mBase + mi*16 + mLane)*SAH + kk + kaLane)*2);
            uint32_t bf[8][2];
            #pragma unroll
            for (int np = 0; np < 4; np++)
                ldsm_x4(bf[np*2][0], bf[np*2][1], bf[np*2+1][0], bf[np*2+1][1],
                        sB + (uint32_t)((nBase + np*16 + nLane)*SAH + kk + kbLane)*2);
            #pragma unroll
            for (int mi = 0; mi < 2; mi++)
                #pragma unroll
                for (int ni = 0; ni < 8; ni++)
                    mma_f16(acc[mi][ni], af[mi], bf[ni]);
        }
    }
#undef ISSUE

    // ---- epilogue ----
    const int rowTile = blockIdx.y * 128;
    const int colTile = blockIdx.x * 128;
    #pragma unroll
    for (int mi = 0; mi < 2; mi++) {
        const int r0 = rowTile + mBase + mi*16 + g;
        #pragma unroll
        for (int ni = 0; ni < 8; ni++) {
            const int c = colTile + nBase + ni*8 + t4*2;
            const float2 bz = *(const float2*)(bias + c);
            float v0 = acc[mi][ni][0] + bz.x;
            float v1 = acc[mi][ni][1] + bz.y;
            float v2 = acc[mi][ni][2] + bz.x;
            float v3 = acc[mi][ni][3] + bz.y;
            const size_t off0 = (size_t)r0 * N + c;
            const size_t off1 = (size_t)(r0 + 8) * N + c;
            if (RES) {
                const float2 ra = *(const float2*)(res + off0);
                const float2 rb = *(const float2*)(res + off1);
                v0 += ra.x; v1 += ra.y; v2 += rb.x; v3 += rb.y;
            }
            if (ACT == 1) {
                v0 = gelu_f(v0); v1 = gelu_f(v1);
                v2 = gelu_f(v2); v3 = gelu_f(v3);
            }
            if (OUTH == 1) {
                __half* C = (__half*)Cv;
                *(__half2*)(C + off0) = __floats2half2_rn(v0, v1);
                *(__half2*)(C + off1) = __floats2half2_rn(v2, v3);
            } else {
                float* C = (float*)Cv;
                *(float2*)(C + off0) = make_float2(v0, v1);
                *(float2*)(C + off1) = make_float2(v2, v3);
                if (OUTH == 2) {
                    *(__half2*)(C2h + off0) = __floats2half2_rn(v0, v1);
                    *(__half2*)(C2h + off1) = __floats2half2_rn(v2, v3);
                }
            }
        }
    }
}

// ---------------- stage 1: factor engineering + time-norm (half out) -----
__global__ void factors_kernel(const float* __restrict__ x,
                               const float* __restrict__ in_w,
                               const float* __restrict__ in_b,
                               __half* __restrict__ feats)
{
    __shared__ float cl[TT], vol[TT];
    __shared__ float sf[TT][TOTF];
    __shared__ float mean_s[TOTF], inv_s[TOTF];
    const int b = blockIdx.x;
    const int t = threadIdx.x;
    const float* xb = x + (size_t)b * TT * FRAW;

    if (t < TT) { cl[t] = xb[t*FRAW + 3]; vol[t] = xb[t*FRAW + 4]; }
    __syncthreads();

    if (t < TT) {
        const float a13 = 2.f/13.f, a27 = 2.f/27.f, a14 = 1.f/14.f;
        float e13 = cl[0], e27 = cl[0];
        float eg = 0.f, el = 0.f;
        for (int j = 1; j <= t; j++) {
            float c = cl[j];
            e13 = a13*c + (1.f - a13)*e13;
            e27 = a27*c + (1.f - a27)*e27;
            float d = c - cl[j-1];
            float gg = fmaxf(d, 0.f);
            float ll = -fminf(d, 0.f);
            eg = a14*gg + (1.f - a14)*eg;
            el = a14*ll + (1.f - a14)*el;
        }
        float macd = e13 - e27;
        float rs  = eg / (el + 1e-10f);
        float rsi = (100.f - 100.f/(1.f + rs)) * 0.01f;

        float bb = 0.f;
        if (t >= 19) {
            float s = 0.f, s2 = 0.f;
            for (int j = t-19; j <= t; j++) { float c = cl[j]; s += c; s2 += c*c; }
            float m  = s * 0.05f;
            float sq = s2 * 0.05f;
            float sd = sqrtf(fmaxf(sq - m*m, 0.f));
            bb = 4.f * sd / (m + 1e-8f);
        }

        float lr = 0.f, lv = 0.f;
        float svt = vol[t] > 0.f ? vol[t] : 1.f;
        if (t >= 1) {
            float pc = fmaxf(cl[t-1], 1e-8f);
            lr = logf(fmaxf(cl[t], 1e-8f) / pc);
            float svp = vol[t-1] > 0.f ? vol[t-1] : 1.f;
            lv = logf(svt / (svp + 1e-8f));
        }

        float vmr = 1.f;
        if (t >= 19) {
            float s = 0.f;
            for (int j = t-19; j <= t; j++) { float v2 = vol[j] > 0.f ? vol[j] : 1.f; s += v2; }
            vmr = svt / (s * 0.05f + 1e-8f);
        }

        float f6[6] = {macd, rsi, bb, lr, lv, vmr};
        #pragma unroll
        for (int f = 0; f < FRAW; f++) sf[t][f] = xb[t*FRAW + f];
        #pragma unroll
        for (int f = 0; f < 6; f++) {
            float v = f6[f];
            if (!isfinite(v)) v = 0.f;
            sf[t][FRAW + f] = v;
        }
    }
    __syncthreads();

    if (t < TOTF) {
        float s = 0.f;
        for (int j = 0; j < TT; j++) s += sf[j][t];
        mean_s[t] = s / (float)TT;
    }
    __syncthreads();
    if (t < TOTF) {
        float m = mean_s[t], s = 0.f;
        for (int j = 0; j < TT; j++) { float d = sf[j][t] - m; s += d*d; }
        inv_s[t] = rsqrtf(s / (float)TT + 1e-5f);
    }
    __syncthreads();

    if (t < TT) {
        const int token = b*NPATCH + (t / PATCH);
        __half* o = feats + (size_t)token*PDIMP + (t % PATCH)*TOTF;
        #pragma unroll
        for (int f = 0; f < TOTF; f++)
            o[f] = __float2half_rn((sf[t][f] - mean_s[f]) * inv_s[f] * in_w[f] + in_b[f]);
    }
    if (t < NPATCH) {
        __half* z = feats + (size_t)(b*NPATCH + t)*PDIMP + PDIM;
        #pragma unroll
        for (int i = 0; i < PDIMP - PDIM; i++) z[i] = __float2half_rn(0.f);
    }
}

// ---------------- LayerNorm: fp32 in, half out ----------------------------
__global__ void __launch_bounds__(128) ln_kernel(const float* __restrict__ X,
                                                 const float* __restrict__ w,
                                                 const float* __restrict__ b,
                                                 __half* __restrict__ Y)
{
    const int row = blockIdx.x;
    const int tid = threadIdx.x;
    const float4 v = ((const float4*)(X + (size_t)row*HID))[tid];
    float s = v.x + v.y + v.z + v.w;
    __shared__ float red[4], red2[4];
    #pragma unroll
    for (int o = 16; o; o >>= 1) s += __shfl_down_sync(0xffffffffu, s, o);
    if ((tid & 31) == 0) red[tid >> 5] = s;
    __syncthreads();
    const float m = (red[0]+red[1]+red[2]+red[3]) * (1.f/(float)HID);
    float dx = v.x - m, dy = v.y - m, dz = v.z - m, dw = v.w - m;
    float s2 = dx*dx + dy*dy + dz*dz + dw*dw;
    #pragma unroll
    for (int o = 16; o; o >>= 1) s2 += __shfl_down_sync(0xffffffffu, s2, o);
    if ((tid & 31) == 0) red2[tid >> 5] = s2;
    __syncthreads();
    const float var = (red2[0]+red2[1]+red2[2]+red2[3]) * (1.f/(float)HID);
    const float inv = rsqrtf(var + 1e-5f);
    const int c = tid * 4;
    const float4 wv = *(const float4*)(w + c);
    const float4 bv = *(const float4*)(b + c);
    __half2* Yp = (__half2*)(Y + (size_t)row*HID);
    Yp[tid*2]   = __floats2half2_rn(dx*inv*wv.x + bv.x, dy*inv*wv.y + bv.y);
    Yp[tid*2+1] = __floats2half2_rn(dz*inv*wv.z + bv.z, dw*inv*wv.w + bv.w);
}

// ---------------- attention: half qkv in, half out ------------------------
__global__ void __launch_bounds__(64) attn_kernel(const __half* __restrict__ qkv,
                                                  __half* __restrict__ out)
{
    const int bh = blockIdx.x;
    const int b = bh >> 3, h = bh & 7;
    const int tid = threadIdx.x;
    __shared__ float q[NPATCH][DH], k[NPATCH][DH], v[NPATCH][DH];
    __shared__ float att[NPATCH][NPATCH];

    const __half* base = qkv + (size_t)(b*NPATCH) * (3*HID) + h*DH;
    for (int idx = tid; idx < NPATCH*DH/2; idx += 64) {
        int p = idx / (DH/2), d2 = idx % (DH/2);
        const __half2 hq = *(const __half2*)(base + (size_t)p*(3*HID)         + d2*2);
        const __half2 hk = *(const __half2*)(base + (size_t)p*(3*HID) + HID   + d2*2);
        const __half2 hv = *(const __half2*)(base + (size_t)p*(3*HID) + 2*HID + d2*2);
        const float2 fq = __half22float2(hq);
        const float2 fk = __half22float2(hk);
        const float2 fv = __half22float2(hv);
        q[p][d2*2] = fq.x; q[p][d2*2+1] = fq.y;
        k[p][d2*2] = fk.x; k[p][d2*2+1] = fk.y;
        v[p][d2*2] = fv.x; v[p][d2*2+1] = fv.y;
    }
    __syncthreads();

    for (int p = tid; p < NPATCH*NPATCH; p += 64) {
        int i = p / NPATCH, j = p % NPATCH;
        float s = 0.f;
        #pragma unroll
        for (int d = 0; d < DH; d++) s = fmaf(q[i][d], k[j][d], s);
        att[i][j] = s * 0.125f;
    }
    __syncthreads();

    if (tid < NPATCH) {
        float mx = -1e30f;
        #pragma unroll
        for (int j = 0; j < NPATCH; j++) mx = fmaxf(mx, att[tid][j]);
        float e[NPATCH], sum = 0.f;
        #pragma unroll
        for (int j = 0; j < NPATCH; j++) { e[j] = expf(att[tid][j] - mx); sum += e[j]; }
        const float r = 1.f / sum;
        #pragma unroll
        for (int j = 0; j < NPATCH; j++) att[tid][j] = e[j] * r;
    }
    __syncthreads();

    const int d = tid;
    #pragma unroll
    for (int i = 0; i < NPATCH; i++) {
        float s = 0.f;
        #pragma unroll
        for (int j = 0; j < NPATCH; j++) s = fmaf(att[i][j], v[j][d], s);
        out[(size_t)(b*NPATCH + i)*HID + h*DH + d] = __float2half_rn(s);
    }
}

// ---------------- final tiny GEMM: (4096x128)@(128x3) --------------------
__global__ void cls3_kernel(const __half* __restrict__ C2,
                            const float* __restrict__ w3,
                            const float* __restrict__ b3,
                            float* __restrict__ out)
{
    const int idx = blockIdx.x * blockDim.x + threadIdx.x;
    if (idx >= BB*NCLS) return;
    const int b = idx / NCLS, c = idx % NCLS;
    float s = b3[c];
    const __half* r = C2 + (size_t)b*128;
    #pragma unroll 8
    for (int k2 = 0; k2 < 128; k2++) s = fmaf(__half2float(r[k2]), w3[k2*NCLS + c], s);
    out[idx] = s;
}

// ---------------- host launcher ------------------------------------------
template<typename T>
static inline T* sym_addr(const void* s) {
    void* p = nullptr;
    cudaGetSymbolAddress(&p, s);
    return (T*)p;
}

template<int ACT, int RES, int OUTH>
static void launch_h(const __half* A, const __half* Bt, const float* bias,
                     const float* res, void* C, __half* C2h, int M, int N, int K)
{
    static bool attr_done = false;
    if (!attr_done) {
        cudaFuncSetAttribute(hgemm_pipe<ACT,RES,OUTH>,
                             cudaFuncAttributeMaxDynamicSharedMemorySize, PIPE_SMEM);
        attr_done = true;
    }
    hgemm_pipe<ACT,RES,OUTH><<<dim3(N/128, M/128), 256, PIPE_SMEM>>>(A, Bt, bias, res, C, C2h, M, N, K);
}

extern "C" void kernel_launch(void* const* d_in, const int* in_sizes, int n_in,
                              void* d_out, int out_size)
{
    const float* x      = (const float*)d_in[0];
    const float* in_w   = (const float*)d_in[1];
    const float* in_b   = (const float*)d_in[2];
    const float* pe_w   = (const float*)d_in[3];
    const float* pe_b   = (const float*)d_in[4];
    const float* ln1_w  = (const float*)d_in[5];
    const float* ln1_b  = (const float*)d_in[6];
    const float* qkv_w  = (const float*)d_in[7];
    const float* qkv_b  = (const float*)d_in[8];
    const float* out_w  = (const float*)d_in[9];
    const float* out_b  = (const float*)d_in[10];
    const float* ln2_w  = (const float*)d_in[11];
    const float* ln2_b  = (const float*)d_in[12];
    const float* mlp_w1 = (const float*)d_in[13];
    const float* mlp_b1 = (const float*)d_in[14];
    const float* mlp_w2 = (const float*)d_in[15];
    const float* mlp_b2 = (const float*)d_in[16];
    const float* cls_w1 = (const float*)d_in[17];
    const float* cls_b1 = (const float*)d_in[18];
    const float* cls_w2 = (const float*)d_in[19];
    const float* cls_b2 = (const float*)d_in[20];
    const float* cls_w3 = (const float*)d_in[21];
    const float* cls_b3 = (const float*)d_in[22];

    __half* F    = sym_addr<__half>(g_feats);
    __half* Nn   = sym_addr<__half>(g_n);
    __half* QKVh = sym_addr<__half>(g_qkvh);
    __half* O    = sym_addr<__half>(g_o);
    __half* G    = sym_addr<__half>(g_g);
    __half* Hh   = sym_addr<__half>(g_hh);
    __half* C1   = sym_addr<__half>(g_c1);
    __half* C2   = sym_addr<__half>(g_c2);
    __half* PEt  = sym_addr<__half>(g_pe_wt);
    __half* QKt  = sym_addr<__half>(g_qkv_wt);
    __half* OUt  = sym_addr<__half>(g_out_wt);
    __half* M1t  = sym_addr<__half>(g_m1_wt);
    __half* M2t  = sym_addr<__half>(g_m2_wt);
    __half* C1t  = sym_addr<__half>(g_c1_wt);
    __half* C2t  = sym_addr<__half>(g_c2_wt);
    float*  H    = sym_addr<float>(g_h);
    float*  H2   = sym_addr<float>(g_h2);

    TJobs jobs;
    jobs.j[0] = { pe_w,   PEt, PDIM, HID,   PDIMP };
    jobs.j[1] = { qkv_w,  QKt, HID,  3*HID, HID   };
    jobs.j[2] = { out_w,  OUt, HID,  HID,   HID   };
    jobs.j[3] = { mlp_w1, M1t, HID,  MLPH,  HID   };
    jobs.j[4] = { mlp_w2, M2t, MLPH, HID,   MLPH  };
    jobs.j[5] = { cls_w1, C1t, HID*NPATCH, 512, HID*NPATCH };
    jobs.j[6] = { cls_w2, C2t, 512,  128,   512   };
    transpose_all<<<TJ_TOTAL_BLOCKS, dim3(32, 8)>>>(jobs);

    factors_kernel<<<BB, TT>>>(x, in_w, in_b, F);

    // patch embed: (TOK x 96) @ (512 x 96)^T -> H fp32
    launch_h<0,0,0>(F, PEt, pe_b, nullptr, H, nullptr, TOK, HID, PDIMP);

    for (int i = 0; i < NL; i++) {
        ln_kernel<<<TOK, 128>>>(H, ln1_w + i*HID, ln1_b + i*HID, Nn);
        launch_h<0,0,1>(Nn, QKt + (size_t)i*3*HID*HID, qkv_b + (size_t)i*3*HID,
                        nullptr, QKVh, nullptr, TOK, 3*HID, HID);
        attn_kernel<<<BB*HEADS, 64>>>(QKVh, O);
        launch_h<0,1,0>(O, OUt + (size_t)i*HID*HID, out_b + (size_t)i*HID,
                        H, H2, nullptr, TOK, HID, HID);
        ln_kernel<<<TOK, 128>>>(H2, ln2_w + i*HID, ln2_b + i*HID, Nn);
        launch_h<1,0,1>(Nn, M1t + (size_t)i*MLPH*HID, mlp_b1 + (size_t)i*MLPH,
                        nullptr, G, nullptr, TOK, MLPH, HID);
        if (i < NL-1) {
            launch_h<0,1,0>(G, M2t + (size_t)i*HID*MLPH, mlp_b2 + (size_t)i*HID,
                            H2, H, nullptr, TOK, HID, MLPH);
        } else {
            launch_h<0,1,2>(G, M2t + (size_t)i*HID*MLPH, mlp_b2 + (size_t)i*HID,
                            H2, H, Hh, TOK, HID, MLPH);
        }
    }

    // classifier: Hh viewed as (4096 x 6144) @ (512 x 6144)^T
    launch_h<1,0,1>(Hh, C1t, cls_b1, nullptr, C1, nullptr, BB, 512, HID*NPATCH);
    launch_h<1,0,1>(C1, C2t, cls_b2, nullptr, C2, nullptr, BB, 128, 512);
    cls3_kernel<<<(BB*NCLS + 127)/128, 128>>>(C2, cls_w3, cls_b3, (float*)d_out);
}